// round 11
// baseline (speedup 1.0000x reference)
#include <cuda_runtime.h>
#include <cuda_bf16.h>
#include <math.h>
#include <stdint.h>

#define B_ 128
#define N_ 1024
#define D_ 512
#define S_ 50
#define M_ (B_ * N_)   // 131072
#define SPAD 64

// ---------------- scratch ----------------------------------------------------
__device__ __nv_bfloat16 g_p0h[(size_t)M_ * D_];
__device__ __nv_bfloat16 g_p0l[(size_t)M_ * D_];
__device__ __nv_bfloat16 g_p1h[(size_t)M_ * D_];
__device__ __nv_bfloat16 g_p1l[(size_t)M_ * D_];
__device__ __nv_bfloat16 g_wh[2][D_ * D_];
__device__ __nv_bfloat16 g_wl[2][D_ * D_];
__device__ __nv_bfloat16 g_v3h[64 * D_];
__device__ __nv_bfloat16 g_v3l[64 * D_];
__device__ float g_db[64];
__device__ float g_dots[(size_t)B_ * N_ * SPAD];
__device__ float g_rowsum[B_ * S_];
__device__ float g_total[B_];
__device__ float g_attn_fb[(size_t)B_ * S_ * N_];
__device__ __nv_bfloat16 g_ath[(size_t)B_ * 64 * N_];
__device__ __nv_bfloat16 g_atl[(size_t)B_ * 64 * N_];

// ---------------- helpers ----------------------------------------------------
__device__ __forceinline__ uint32_t smem_u32(const void* p) {
    uint32_t a;
    asm("{ .reg .u64 t; cvta.to.shared.u64 t, %1; cvt.u32.u64 %0, t; }" : "=r"(a) : "l"(p));
    return a;
}
__device__ __forceinline__ void ldsm_x4(uint32_t* r, uint32_t addr) {
    asm volatile("ldmatrix.sync.aligned.m8n8.x4.shared.b16 {%0,%1,%2,%3}, [%4];"
                 : "=r"(r[0]), "=r"(r[1]), "=r"(r[2]), "=r"(r[3]) : "r"(addr));
}
__device__ __forceinline__ void ldsm_x4_t(uint32_t* r, uint32_t addr) {
    asm volatile("ldmatrix.sync.aligned.m8n8.x4.trans.shared.b16 {%0,%1,%2,%3}, [%4];"
                 : "=r"(r[0]), "=r"(r[1]), "=r"(r[2]), "=r"(r[3]) : "r"(addr));
}
__device__ __forceinline__ void mma_bf16(float* d, const uint32_t* a, const uint32_t* b) {
    asm volatile("mma.sync.aligned.m16n8k16.row.col.f32.bf16.bf16.f32 "
                 "{%0,%1,%2,%3},{%4,%5,%6,%7},{%8,%9},{%0,%1,%2,%3};"
                 : "+f"(d[0]), "+f"(d[1]), "+f"(d[2]), "+f"(d[3])
                 : "r"(a[0]), "r"(a[1]), "r"(a[2]), "r"(a[3]), "r"(b[0]), "r"(b[1]));
}
__device__ __forceinline__ void cp16(uint32_t dst, const void* src) {
    asm volatile("cp.async.cg.shared.global [%0], [%1], 16;" :: "r"(dst), "l"(src));
}
#define CP_COMMIT() asm volatile("cp.async.commit_group;" ::: "memory")
#define CP_WAIT1()  asm volatile("cp.async.wait_group 1;" ::: "memory")
#define CP_WAIT0()  asm volatile("cp.async.wait_group 0;" ::: "memory")

__device__ __forceinline__ uint32_t pack_bf16(__nv_bfloat16 a, __nv_bfloat16 b) {
    __nv_bfloat162 t = __halves2bfloat162(a, b);
    return *reinterpret_cast<uint32_t*>(&t);
}
__device__ __forceinline__ void split4(float4 v, uint2& hi, uint2& lo) {
    __nv_bfloat16 hx = __float2bfloat16(v.x), hy = __float2bfloat16(v.y);
    __nv_bfloat16 hz = __float2bfloat16(v.z), hw = __float2bfloat16(v.w);
    __nv_bfloat16 lx = __float2bfloat16(v.x - __bfloat162float(hx));
    __nv_bfloat16 ly = __float2bfloat16(v.y - __bfloat162float(hy));
    __nv_bfloat16 lz = __float2bfloat16(v.z - __bfloat162float(hz));
    __nv_bfloat16 lw = __float2bfloat16(v.w - __bfloat162float(hw));
    hi = make_uint2(pack_bf16(hx, hy), pack_bf16(hz, hw));
    lo = make_uint2(pack_bf16(lx, ly), pack_bf16(lz, lw));
}

// ---------------- misc small kernels ------------------------------------------
__global__ void sc_split_kernel(const float* __restrict__ src, __nv_bfloat16* __restrict__ hi,
                                __nv_bfloat16* __restrict__ lo, int n4) {
    int i = blockIdx.x * blockDim.x + threadIdx.x;
    if (i < n4) {
        float4 v = ((const float4*)src)[i];
        uint2 h, l;
        split4(v, h, l);
        ((uint2*)hi)[i] = h;
        ((uint2*)lo)[i] = l;
    }
}

// V3[i,:] = slots[i,:] @ W3 (bf16 hi/lo); db[i] = b3 . slots[i]
__global__ __launch_bounds__(256)
void sc_v3_kernel(const float* __restrict__ slots, const float* __restrict__ W3,
                  const float* __restrict__ b3) {
    int i = blockIdx.x;
    int ebase = blockIdx.y * 64;
    __shared__ float srow[D_];
    for (int d = threadIdx.x; d < D_; d += 256)
        srow[d] = (i < S_) ? slots[i * D_ + d] : 0.0f;
    __syncthreads();
    int el = threadIdx.x >> 2, ks = threadIdx.x & 3;
    int e = ebase + el;
    float s = 0.0f;
    #pragma unroll 8
    for (int d = ks * 128; d < ks * 128 + 128; d++)
        s = fmaf(srow[d], W3[(size_t)d * D_ + e], s);
    s += __shfl_xor_sync(0xffffffffu, s, 1);
    s += __shfl_xor_sync(0xffffffffu, s, 2);
    if (ks == 0) {
        __nv_bfloat16 h = __float2bfloat16(s);
        __nv_bfloat16 l = __float2bfloat16(s - __bfloat162float(h));
        g_v3h[i * D_ + e] = h;
        g_v3l[i * D_ + e] = l;
    }
    if (blockIdx.y == 0) {
        __shared__ float red[256];
        float p = 0.0f;
        for (int d = threadIdx.x; d < D_; d += 256) p = fmaf(b3[d], srow[d], p);
        red[threadIdx.x] = p;
        __syncthreads();
        for (int w = 128; w > 0; w >>= 1) {
            if (threadIdx.x < w) red[threadIdx.x] += red[threadIdx.x + w];
            __syncthreads();
        }
        if (threadIdx.x == 0) g_db[i] = red[0];
    }
}

// ---------------- pipelined bf16-split GEMM (MLP layers) -----------------------
// CTA tile 128m x 256n, BK=32, 8 warps with 64x64 warp tiles, 2-stage cp.async.
// Stage (61440 B): Ahi@0 (128x80), Alo@10240, Bhi@20480 (256x80), Blo@40960.
#define GSTAGE 61440
#define GSMEM  (2 * GSTAGE)
template<int RELU>
__global__ __launch_bounds__(256, 1)
void sc_pipe_gemm(const __nv_bfloat16* __restrict__ Ahi, const __nv_bfloat16* __restrict__ Alo,
                  const __nv_bfloat16* __restrict__ Bhi, const __nv_bfloat16* __restrict__ Blo,
                  const float* __restrict__ bias,
                  __nv_bfloat16* __restrict__ Chi, __nv_bfloat16* __restrict__ Clo) {
    extern __shared__ char sm[];
    const int tid = threadIdx.x;
    const int wid = tid >> 5, lane = tid & 31;
    const int wm = wid & 1, wn = wid >> 1;        // warp tile (wm*64 m, wn*64 n)
    const int mbase = blockIdx.y * 128;
    const int nbase = blockIdx.x * 256;
    const uint32_t sb = smem_u32(sm);

    const __nv_bfloat16* Ah = Ahi + (size_t)mbase * D_;
    const __nv_bfloat16* Al = Alo + (size_t)mbase * D_;
    const __nv_bfloat16* Bh = Bhi + (size_t)nbase * D_;
    const __nv_bfloat16* Bl = Blo + (size_t)nbase * D_;

    // A producer: 2 chunks per thread; B producer: row = tid, 4 chunks
    const int idx0 = tid * 2;
    const int prow0 = idx0 >> 2,        pch0 = (idx0 & 3);
    const int prow1 = (idx0 + 1) >> 2,  pch1 = ((idx0 + 1) & 3);

    float brg[8][2];
    #pragma unroll
    for (int nf = 0; nf < 8; nf++) {
        int col = nbase + wn * 64 + nf * 8 + (lane & 3) * 2;
        brg[nf][0] = bias[col];
        brg[nf][1] = bias[col + 1];
    }

    float acc[4][8][4];
    #pragma unroll
    for (int a = 0; a < 4; a++)
        #pragma unroll
        for (int b = 0; b < 8; b++)
            #pragma unroll
            for (int c = 0; c < 4; c++) acc[a][b][c] = 0.0f;

    const uint32_t a_l = sb + (uint32_t)((wm * 64 + (lane & 15)) * 80 + (lane >> 4) * 16);
    const uint32_t b_l = sb + 20480u +
        (uint32_t)((wn * 64 + ((lane >> 4) & 1) * 8 + (lane & 7)) * 80 + ((lane >> 3) & 1) * 16);

    auto ISSUE = [&](int stage, int slab) {
        const int k0 = slab * 32;
        const uint32_t base = sb + (uint32_t)stage * GSTAGE;
        // A hi/lo: 512 chunks each
        uint32_t d0 = base + (uint32_t)prow0 * 80u + (uint32_t)pch0 * 16u;
        uint32_t d1 = base + (uint32_t)prow1 * 80u + (uint32_t)pch1 * 16u;
        size_t s0 = (size_t)prow0 * D_ + k0 + pch0 * 8;
        size_t s1 = (size_t)prow1 * D_ + k0 + pch1 * 8;
        cp16(d0,          Ah + s0);  cp16(d1,          Ah + s1);
        cp16(d0 + 10240u, Al + s0);  cp16(d1 + 10240u, Al + s1);
        // B hi/lo: row = tid, 4 chunks
        uint32_t db_ = base + 20480u + (uint32_t)tid * 80u;
        const __nv_bfloat16* bhrow = Bh + (size_t)tid * D_ + k0;
        const __nv_bfloat16* blrow = Bl + (size_t)tid * D_ + k0;
        #pragma unroll
        for (int q = 0; q < 4; q++) {
            cp16(db_ + q * 16u,          bhrow + q * 8);
            cp16(db_ + 20480u + q * 16u, blrow + q * 8);
        }
        CP_COMMIT();
    };

    auto COMP = [&](int stage) {
        uint32_t ab  = a_l + (uint32_t)stage * GSTAGE;
        uint32_t bb_ = b_l + (uint32_t)stage * GSTAGE;
        #pragma unroll
        for (int ks = 0; ks < 2; ks++) {
            uint32_t ak = ab + ks * 32;
            uint32_t bk = bb_ + ks * 32;
            uint32_t af[4][4], b0[4][4], b1[4][4];
            // term 1: ahi * bhi
            #pragma unroll
            for (int mf = 0; mf < 4; mf++) ldsm_x4(af[mf], ak + mf * 1280);
            #pragma unroll
            for (int p = 0; p < 4; p++) ldsm_x4(b0[p], bk + p * 1280);
            #pragma unroll
            for (int mf = 0; mf < 4; mf++)
                #pragma unroll
                for (int nf = 0; nf < 8; nf++)
                    mma_bf16(acc[mf][nf], af[mf], &b0[nf >> 1][(nf & 1) * 2]);
            // term 2: ahi * blo
            #pragma unroll
            for (int p = 0; p < 4; p++) ldsm_x4(b1[p], bk + 20480u + p * 1280);
            #pragma unroll
            for (int mf = 0; mf < 4; mf++)
                #pragma unroll
                for (int nf = 0; nf < 8; nf++)
                    mma_bf16(acc[mf][nf], af[mf], &b1[nf >> 1][(nf & 1) * 2]);
            // term 3: alo * bhi (overwrite af)
            #pragma unroll
            for (int mf = 0; mf < 4; mf++) ldsm_x4(af[mf], ak + 10240u + mf * 1280);
            #pragma unroll
            for (int mf = 0; mf < 4; mf++)
                #pragma unroll
                for (int nf = 0; nf < 8; nf++)
                    mma_bf16(acc[mf][nf], af[mf], &b0[nf >> 1][(nf & 1) * 2]);
        }
    };

    ISSUE(0, 0);
    ISSUE(1, 1);
    for (int i = 0; i < 16; i++) {
        if (i < 15) { CP_WAIT1(); } else { CP_WAIT0(); }
        __syncthreads();
        COMP(i & 1);
        __syncthreads();
        if (i < 14) ISSUE(i & 1, i + 2);
    }

    #pragma unroll
    for (int mf = 0; mf < 4; mf++) {
        int row0 = mbase + wm * 64 + mf * 16 + (lane >> 2);
        #pragma unroll
        for (int nf = 0; nf < 8; nf++) {
            int col = nbase + wn * 64 + nf * 8 + (lane & 3) * 2;
            float2 v0, v1;
            v0.x = acc[mf][nf][0] + brg[nf][0];
            v0.y = acc[mf][nf][1] + brg[nf][1];
            v1.x = acc[mf][nf][2] + brg[nf][0];
            v1.y = acc[mf][nf][3] + brg[nf][1];
            if (RELU) {
                v0.x = fmaxf(v0.x, 0.f); v0.y = fmaxf(v0.y, 0.f);
                v1.x = fmaxf(v1.x, 0.f); v1.y = fmaxf(v1.y, 0.f);
            }
            __nv_bfloat16 h0 = __float2bfloat16(v0.x), h1 = __float2bfloat16(v0.y);
            __nv_bfloat16 h2 = __float2bfloat16(v1.x), h3 = __float2bfloat16(v1.y);
            __nv_bfloat16 l0 = __float2bfloat16(v0.x - __bfloat162float(h0));
            __nv_bfloat16 l1 = __float2bfloat16(v0.y - __bfloat162float(h1));
            __nv_bfloat16 l2 = __float2bfloat16(v1.x - __bfloat162float(h2));
            __nv_bfloat16 l3 = __float2bfloat16(v1.y - __bfloat162float(h3));
            *(uint32_t*)&Chi[(size_t)row0 * D_ + col]       = pack_bf16(h0, h1);
            *(uint32_t*)&Chi[(size_t)(row0 + 8) * D_ + col] = pack_bf16(h2, h3);
            *(uint32_t*)&Clo[(size_t)row0 * D_ + col]       = pack_bf16(l0, l1);
            *(uint32_t*)&Clo[(size_t)(row0 + 8) * D_ + col] = pack_bf16(l2, l3);
        }
    }
}

// ---------------- dots via mma ---------------------------------------------------
#define DSTAGE 30720
#define DSMEM  (2 * DSTAGE)
__global__ __launch_bounds__(256, 2)
void sc_dots_mma(const __nv_bfloat16* __restrict__ Ahi, const __nv_bfloat16* __restrict__ Alo) {
    extern __shared__ char sm[];
    const int tid = threadIdx.x;
    const int wid = tid >> 5, lane = tid & 31;
    const int mbase = blockIdx.x * 128;
    const uint32_t sb = smem_u32(sm);
    __shared__ float sdb[64];
    if (tid < 64) sdb[tid] = g_db[tid];

    const __nv_bfloat16* Ah = Ahi + (size_t)mbase * D_;
    const __nv_bfloat16* Al = Alo + (size_t)mbase * D_;

    const int prow = tid >> 1, pch0 = (tid & 1) * 2, pch1 = pch0 + 1;
    const int brow = tid >> 2, bch = tid & 3;

    float acc[8][4];
    #pragma unroll
    for (int u = 0; u < 8; u++)
        #pragma unroll
        for (int v = 0; v < 4; v++) acc[u][v] = 0.0f;

    const uint32_t a_l = sb + (uint32_t)((wid * 16 + (lane & 15)) * 80 + (lane >> 4) * 16);
    const uint32_t b_l = sb + 20480u +
        (uint32_t)((((lane >> 4) & 1) * 8 + (lane & 7)) * 80 + ((lane >> 3) & 1) * 16);

    auto ISSUE = [&](int stage, int slab) {
        const int k0 = slab * 32;
        const uint32_t base = sb + (uint32_t)stage * DSTAGE;
        uint32_t d0 = base + (uint32_t)prow * 80u + (uint32_t)pch0 * 16u;
        size_t s0 = (size_t)prow * D_ + k0 + pch0 * 8;
        size_t s1 = (size_t)prow * D_ + k0 + pch1 * 8;
        cp16(d0,          Ah + s0);  cp16(d0 + 16u,          Ah + s1);
        cp16(d0 + 10240u, Al + s0);  cp16(d0 + 10240u + 16u, Al + s1);
        uint32_t db_ = base + 20480u + (uint32_t)brow * 80u + (uint32_t)bch * 16u;
        size_t sB = (size_t)brow * D_ + k0 + bch * 8;
        cp16(db_,         g_v3h + sB);
        cp16(db_ + 5120u, g_v3l + sB);
        CP_COMMIT();
    };

    auto COMP = [&](int stage) {
        uint32_t ab  = a_l + (uint32_t)stage * DSTAGE;
        uint32_t bb_ = b_l + (uint32_t)stage * DSTAGE;
        #pragma unroll
        for (int ks = 0; ks < 2; ks++) {
            uint32_t ak = ab + ks * 32;
            uint32_t bk = bb_ + ks * 32;
            uint32_t af[4], bh[4][4], bl[4][4];
            ldsm_x4(af, ak);
            #pragma unroll
            for (int p = 0; p < 4; p++) ldsm_x4(bh[p], bk + p * 1280);
            #pragma unroll
            for (int nf = 0; nf < 8; nf++)
                mma_bf16(acc[nf], af, &bh[nf >> 1][(nf & 1) * 2]);
            #pragma unroll
            for (int p = 0; p < 4; p++) ldsm_x4(bl[p], bk + 5120 + p * 1280);
            #pragma unroll
            for (int nf = 0; nf < 8; nf++)
                mma_bf16(acc[nf], af, &bl[nf >> 1][(nf & 1) * 2]);
            ldsm_x4(af, ak + 10240);
            #pragma unroll
            for (int nf = 0; nf < 8; nf++)
                mma_bf16(acc[nf], af, &bh[nf >> 1][(nf & 1) * 2]);
        }
    };

    ISSUE(0, 0);
    ISSUE(1, 1);
    for (int i = 0; i < 16; i++) {
        if (i < 15) { CP_WAIT1(); } else { CP_WAIT0(); }
        __syncthreads();
        COMP(i & 1);
        __syncthreads();
        if (i < 14) ISSUE(i & 1, i + 2);
    }

    const float scale = 0.04419417382415922f;
    const int b  = mbase / N_;
    const int jb = mbase % N_;
    const int r0 = jb + wid * 16 + (lane >> 2);
    #pragma unroll
    for (int nf = 0; nf < 8; nf++) {
        int col = nf * 8 + (lane & 3) * 2;
        float dbx = sdb[col], dby = sdb[col + 1];
        float2 v0, v1;
        v0.x = (acc[nf][0] + dbx) * scale;
        v0.y = (acc[nf][1] + dby) * scale;
        v1.x = (acc[nf][2] + dbx) * scale;
        v1.y = (acc[nf][3] + dby) * scale;
        *(float2*)&g_dots[((size_t)b * N_ + r0) * SPAD + col]     = v0;
        *(float2*)&g_dots[((size_t)b * N_ + r0 + 8) * SPAD + col] = v1;
    }
}

// ---------------- rowsum + total ---------------------------------------------
__global__ __launch_bounds__(256)
void sc_rowsum_kernel() {
    int b = blockIdx.x;
    int i = threadIdx.x & 63;
    int q = threadIdx.x >> 6;
    __shared__ float red[4][64];
    __shared__ float tot[64];
    float s = 0.0f;
    for (int j = q * 256; j < q * 256 + 256; j++)
        s += g_dots[((size_t)b * N_ + j) * SPAD + i];
    red[q][i] = s;
    __syncthreads();
    if (threadIdx.x < 64) {
        float r = red[0][threadIdx.x] + red[1][threadIdx.x] +
                  red[2][threadIdx.x] + red[3][threadIdx.x];
        if (threadIdx.x < S_) g_rowsum[b * S_ + threadIdx.x] = r;
        tot[threadIdx.x] = (threadIdx.x < S_) ? r : 0.0f;
    }
    __syncthreads();
    if (threadIdx.x < 32) {
        float t = tot[threadIdx.x] + tot[threadIdx.x + 32];
        #pragma unroll
        for (int w = 16; w > 0; w >>= 1) t += __shfl_down_sync(0xffffffffu, t, w);
        if (threadIdx.x == 0) g_total[b] = t;
    }
}

// ---------------- softmax (also emits attn hi/lo bf16) --------------------------
__global__ __launch_bounds__(128)
void sc_softmax_kernel(float* __restrict__ attn_out) {
    int b = blockIdx.y;
    int j = blockIdx.x * 128 + threadIdx.x;
    __shared__ float inv_rs[S_];
    if (threadIdx.x < S_) inv_rs[threadIdx.x] = 1.0f / g_rowsum[b * S_ + threadIdx.x];
    __syncthreads();
    float tot = g_total[b];
    const float* src = &g_dots[((size_t)b * N_ + j) * SPAD];
    float dn[S_];
    float m = -INFINITY;
    #pragma unroll
    for (int i = 0; i < S_; i++) {
        float v = src[i] * inv_rs[i] * tot;
        dn[i] = v;
        m = fmaxf(m, v);
    }
    float s = 0.f;
    #pragma unroll
    for (int i = 0; i < S_; i++) s += expf(dn[i] - m);
    float inv_s = 1.0f / s;
    #pragma unroll
    for (int i = 0; i < S_; i++) {
        float sm  = expf(dn[i] - m) * inv_s;
        float sig = 1.0f / (1.0f + expf(-dn[i]));
        float a = sm * sig;
        attn_out[((size_t)b * S_ + i) * N_ + j] = a;
        __nv_bfloat16 h = __float2bfloat16(a);
        __nv_bfloat16 l = __float2bfloat16(a - __bfloat162float(h));
        g_ath[((size_t)b * 64 + i) * N_ + j] = h;
        g_atl[((size_t)b * 64 + i) * N_ + j] = l;
    }
}

// ---------------- updates via mma -----------------------------------------------
#define USTAGE 27648
#define USMEM  (2 * USTAGE)
__global__ __launch_bounds__(256, 2)
void sc_updates_mma(const float* __restrict__ inputs, float* __restrict__ out) {
    extern __shared__ char sm[];
    const int tid = threadIdx.x;
    const int wid = tid >> 5, lane = tid & 31;
    const int wm = wid & 1, wn = wid >> 1;
    const int b = blockIdx.y;
    const int dtile = blockIdx.x * 128;
    const uint32_t sb = smem_u32(sm);

    const __nv_bfloat16* Ah = g_ath + (size_t)b * 64 * N_;
    const __nv_bfloat16* Al = g_atl + (size_t)b * 64 * N_;
    const float* Bsrc = inputs + (size_t)b * N_ * D_ + dtile;

    const int arow = tid >> 2, ach = tid & 3;
    const int brow = tid >> 3, bdc = (tid & 7) * 16;

    float acc[2][4][4];
    #pragma unroll
    for (int a = 0; a < 2; a++)
        #pragma unroll
        for (int c = 0; c < 4; c++)
            #pragma unroll
            for (int e = 0; e < 4; e++) acc[a][c][e] = 0.0f;

    const uint32_t a_l = sb + (uint32_t)((wm * 32 + (lane & 15)) * 80 + (lane >> 4) * 16);
    const uint32_t b_l = sb + 10240u +
        (uint32_t)((((lane >> 3) & 1) * 8 + (lane & 7)) * 272 +
                   (wn * 32 + (lane >> 4) * 8) * 2);

    auto ISSUE_A = [&](int stage, int slab) {
        const uint32_t base = sb + (uint32_t)stage * USTAGE;
        uint32_t d0 = base + (uint32_t)arow * 80u + (uint32_t)ach * 16u;
        size_t s0 = (size_t)arow * N_ + slab * 32 + ach * 8;
        cp16(d0,         Ah + s0);
        cp16(d0 + 5120u, Al + s0);
        CP_COMMIT();
    };

    float4 breg[2][4];
    auto LDGB = [&](int slab, int buf) {
        const float* p = Bsrc + (size_t)(slab * 32 + brow) * D_ + bdc;
        #pragma unroll
        for (int q = 0; q < 4; q++) breg[buf][q] = *(const float4*)(p + q * 4);
    };
    auto STSB = [&](int stage, int buf) {
        const uint32_t base = sb + (uint32_t)stage * USTAGE + 10240u +
                              (uint32_t)brow * 272u + (uint32_t)bdc * 2u;
        #pragma unroll
        for (int q = 0; q < 4; q++) {
            uint2 h, l;
            split4(breg[buf][q], h, l);
            *(uint2*)(sm + (base - sb) + q * 8)         = h;
            *(uint2*)(sm + (base - sb) + 8704u + q * 8) = l;
        }
    };

    auto COMP = [&](int stage) {
        uint32_t ab  = a_l + (uint32_t)stage * USTAGE;
        uint32_t bb_ = b_l + (uint32_t)stage * USTAGE;
        #pragma unroll
        for (int ks = 0; ks < 2; ks++) {
            uint32_t ak = ab + ks * 32;
            uint32_t bk = bb_ + ks * 16 * 272;
            uint32_t af[2][4], bh[2][4], bl[2][4];
            #pragma unroll
            for (int mf = 0; mf < 2; mf++) ldsm_x4(af[mf], ak + mf * 1280);
            #pragma unroll
            for (int p = 0; p < 2; p++) ldsm_x4_t(bh[p], bk + p * 32);
            #pragma unroll
            for (int mf = 0; mf < 2; mf++)
                #pragma unroll
                for (int nf = 0; nf < 4; nf++)
                    mma_bf16(acc[mf][nf], af[mf], &bh[nf >> 1][(nf & 1) * 2]);
            #pragma unroll
            for (int p = 0; p < 2; p++) ldsm_x4_t(bl[p], bk + 8704u + p * 32);
            #pragma unroll
            for (int mf = 0; mf < 2; mf++)
                #pragma unroll
                for (int nf = 0; nf < 4; nf++)
                    mma_bf16(acc[mf][nf], af[mf], &bl[nf >> 1][(nf & 1) * 2]);
            #pragma unroll
            for (int mf = 0; mf < 2; mf++) ldsm_x4(af[mf], ak + 5120u + mf * 1280);
            #pragma unroll
            for (int mf = 0; mf < 2; mf++)
                #pragma unroll
                for (int nf = 0; nf < 4; nf++)
                    mma_bf16(acc[mf][nf], af[mf], &bh[nf >> 1][(nf & 1) * 2]);
        }
    };

    LDGB(0, 0);
    ISSUE_A(0, 0);
    ISSUE_A(1, 1);
    for (int i = 0; i < 32; i++) {
        const int s = i & 1;
        if (i < 31) LDGB(i + 1, s ^ 1);
        if (i < 31) { CP_WAIT1(); } else { CP_WAIT0(); }
        __syncthreads();
        STSB(s, s);
        __syncthreads();
        COMP(s);
        __syncthreads();
        if (i < 30) ISSUE_A(s, i + 2);
    }

    const float invd = 1.0f / (float)D_;
    #pragma unroll
    for (int mf = 0; mf < 2; mf++) {
        int i0 = wm * 32 + mf * 16 + (lane >> 2);
        #pragma unroll
        for (int nf = 0; nf < 4; nf++) {
            int col = dtile + wn * 32 + nf * 8 + (lane & 3) * 2;
            if (i0 < S_) {
                float2 v;
                v.x = acc[mf][nf][0] * invd;
                v.y = acc[mf][nf][1] * invd;
                *(float2*)&out[((size_t)b * S_ + i0) * D_ + col] = v;
            }
            if (i0 + 8 < S_) {
                float2 v;
                v.x = acc[mf][nf][2] * invd;
                v.y = acc[mf][nf][3] * invd;
                *(float2*)&out[((size_t)b * S_ + i0 + 8) * D_ + col] = v;
            }
        }
    }
}

// ---------------- launch ---------------------------------------------------------
extern "C" void kernel_launch(void* const* d_in, const int* in_sizes, int n_in,
                              void* d_out, int out_size) {
    const float* inputs_pe = (const float*)d_in[0];
    const float* inputs    = (const float*)d_in[1];
    const float* slots     = (const float*)d_in[2];
    const float* W1 = (const float*)d_in[3];
    const float* b1 = (const float*)d_in[4];
    const float* W2 = (const float*)d_in[5];
    const float* b2 = (const float*)d_in[6];
    const float* W3 = (const float*)d_in[7];
    const float* b3 = (const float*)d_in[8];
    float* out = (float*)d_out;

    __nv_bfloat16 *p0h, *p0l, *p1h, *p1l, *wh, *wl;
    float *attn_fb;
    cudaGetSymbolAddress((void**)&p0h, g_p0h);
    cudaGetSymbolAddress((void**)&p0l, g_p0l);
    cudaGetSymbolAddress((void**)&p1h, g_p1h);
    cudaGetSymbolAddress((void**)&p1l, g_p1l);
    cudaGetSymbolAddress((void**)&wh,  g_wh);
    cudaGetSymbolAddress((void**)&wl,  g_wl);
    cudaGetSymbolAddress((void**)&attn_fb, g_attn_fb);

    const size_t updates_elems = (size_t)B_ * S_ * D_;
    const size_t attn_elems    = (size_t)B_ * S_ * N_;
    float* attn_ptr = out + updates_elems;
    if ((size_t)out_size < updates_elems + attn_elems) attn_ptr = attn_fb;

    cudaFuncSetAttribute(sc_pipe_gemm<1>, cudaFuncAttributeMaxDynamicSharedMemorySize, GSMEM);
    cudaFuncSetAttribute(sc_dots_mma,     cudaFuncAttributeMaxDynamicSharedMemorySize, DSMEM);
    cudaFuncSetAttribute(sc_updates_mma,  cudaFuncAttributeMaxDynamicSharedMemorySize, USMEM);

    {
        int n4 = (M_ * D_) / 4;
        sc_split_kernel<<<(n4 + 255) / 256, 256>>>(inputs_pe, p0h, p0l, n4);
        int w4 = (D_ * D_) / 4;
        sc_split_kernel<<<(w4 + 255) / 256, 256>>>(W1, wh + 0 * D_ * D_, wl + 0 * D_ * D_, w4);
        sc_split_kernel<<<(w4 + 255) / 256, 256>>>(W2, wh + 1 * D_ * D_, wl + 1 * D_ * D_, w4);
    }
    {
        dim3 gv3(64, 8);
        sc_v3_kernel<<<gv3, 256>>>(slots, W3, b3);
    }

    dim3 gg(D_ / 256, M_ / 128);
    sc_pipe_gemm<1><<<gg, 256, GSMEM>>>(p0h, p0l, wh + 0 * D_ * D_, wl + 0 * D_ * D_, b1,
                                        p1h, p1l);
    sc_pipe_gemm<1><<<gg, 256, GSMEM>>>(p1h, p1l, wh + 1 * D_ * D_, wl + 1 * D_ * D_, b2,
                                        p0h, p0l);

    sc_dots_mma<<<M_ / 128, 256, DSMEM>>>(p0h, p0l);
    sc_rowsum_kernel<<<B_, 256>>>();

    dim3 gsm(N_ / 128, B_);
    sc_softmax_kernel<<<gsm, 128>>>(attn_ptr);

    dim3 gup(D_ / 128, B_);
    sc_updates_mma<<<gup, 256, USMEM>>>(inputs, out);
}

// round 12
// speedup vs baseline: 1.0536x; 1.0536x over previous
#include <cuda_runtime.h>
#include <cuda_bf16.h>
#include <math.h>
#include <stdint.h>

#define B_ 128
#define N_ 1024
#define D_ 512
#define S_ 50
#define M_ (B_ * N_)   // 131072
#define SPAD 64

// ---------------- scratch ----------------------------------------------------
__device__ __nv_bfloat16 g_p0h[(size_t)M_ * D_];
__device__ __nv_bfloat16 g_p0l[(size_t)M_ * D_];
__device__ __nv_bfloat16 g_p1h[(size_t)M_ * D_];
__device__ __nv_bfloat16 g_p1l[(size_t)M_ * D_];
__device__ __nv_bfloat16 g_wh[2][D_ * D_];
__device__ __nv_bfloat16 g_wl[2][D_ * D_];
__device__ __nv_bfloat16 g_v3h[64 * D_];
__device__ __nv_bfloat16 g_v3l[64 * D_];
__device__ float g_db[64];
__device__ float g_dots[(size_t)B_ * N_ * SPAD];
__device__ float g_rowsum[B_ * S_];
__device__ float g_total[B_];
__device__ float g_attn_fb[(size_t)B_ * S_ * N_];
__device__ __nv_bfloat16 g_ath[(size_t)B_ * 64 * N_];
__device__ __nv_bfloat16 g_atl[(size_t)B_ * 64 * N_];

// ---------------- helpers ----------------------------------------------------
__device__ __forceinline__ uint32_t smem_u32(const void* p) {
    uint32_t a;
    asm("{ .reg .u64 t; cvta.to.shared.u64 t, %1; cvt.u32.u64 %0, t; }" : "=r"(a) : "l"(p));
    return a;
}
__device__ __forceinline__ void ldsm_x4(uint32_t* r, uint32_t addr) {
    asm volatile("ldmatrix.sync.aligned.m8n8.x4.shared.b16 {%0,%1,%2,%3}, [%4];"
                 : "=r"(r[0]), "=r"(r[1]), "=r"(r[2]), "=r"(r[3]) : "r"(addr));
}
__device__ __forceinline__ void ldsm_x4_t(uint32_t* r, uint32_t addr) {
    asm volatile("ldmatrix.sync.aligned.m8n8.x4.trans.shared.b16 {%0,%1,%2,%3}, [%4];"
                 : "=r"(r[0]), "=r"(r[1]), "=r"(r[2]), "=r"(r[3]) : "r"(addr));
}
__device__ __forceinline__ void mma_bf16(float* d, const uint32_t* a, const uint32_t* b) {
    asm volatile("mma.sync.aligned.m16n8k16.row.col.f32.bf16.bf16.f32 "
                 "{%0,%1,%2,%3},{%4,%5,%6,%7},{%8,%9},{%0,%1,%2,%3};"
                 : "+f"(d[0]), "+f"(d[1]), "+f"(d[2]), "+f"(d[3])
                 : "r"(a[0]), "r"(a[1]), "r"(a[2]), "r"(a[3]), "r"(b[0]), "r"(b[1]));
}
__device__ __forceinline__ void cp16(uint32_t dst, const void* src) {
    asm volatile("cp.async.cg.shared.global [%0], [%1], 16;" :: "r"(dst), "l"(src));
}
#define CP_COMMIT() asm volatile("cp.async.commit_group;" ::: "memory")
#define CP_WAIT1()  asm volatile("cp.async.wait_group 1;" ::: "memory")
#define CP_WAIT0()  asm volatile("cp.async.wait_group 0;" ::: "memory")

__device__ __forceinline__ uint32_t pack_bf16(__nv_bfloat16 a, __nv_bfloat16 b) {
    __nv_bfloat162 t = __halves2bfloat162(a, b);
    return *reinterpret_cast<uint32_t*>(&t);
}
__device__ __forceinline__ void split4(float4 v, uint2& hi, uint2& lo) {
    __nv_bfloat16 hx = __float2bfloat16(v.x), hy = __float2bfloat16(v.y);
    __nv_bfloat16 hz = __float2bfloat16(v.z), hw = __float2bfloat16(v.w);
    __nv_bfloat16 lx = __float2bfloat16(v.x - __bfloat162float(hx));
    __nv_bfloat16 ly = __float2bfloat16(v.y - __bfloat162float(hy));
    __nv_bfloat16 lz = __float2bfloat16(v.z - __bfloat162float(hz));
    __nv_bfloat16 lw = __float2bfloat16(v.w - __bfloat162float(hw));
    hi = make_uint2(pack_bf16(hx, hy), pack_bf16(hz, hw));
    lo = make_uint2(pack_bf16(lx, ly), pack_bf16(lz, lw));
}

// ---------------- misc small kernels ------------------------------------------
__global__ void sc_split_kernel(const float* __restrict__ src, __nv_bfloat16* __restrict__ hi,
                                __nv_bfloat16* __restrict__ lo, int n4) {
    int i = blockIdx.x * blockDim.x + threadIdx.x;
    if (i < n4) {
        float4 v = ((const float4*)src)[i];
        uint2 h, l;
        split4(v, h, l);
        ((uint2*)hi)[i] = h;
        ((uint2*)lo)[i] = l;
    }
}

// V3[i,:] = slots[i,:] @ W3 (bf16 hi/lo); db[i] = b3 . slots[i]
__global__ __launch_bounds__(256)
void sc_v3_kernel(const float* __restrict__ slots, const float* __restrict__ W3,
                  const float* __restrict__ b3) {
    int i = blockIdx.x;
    int ebase = blockIdx.y * 64;
    __shared__ float srow[D_];
    for (int d = threadIdx.x; d < D_; d += 256)
        srow[d] = (i < S_) ? slots[i * D_ + d] : 0.0f;
    __syncthreads();
    int el = threadIdx.x >> 2, ks = threadIdx.x & 3;
    int e = ebase + el;
    float s = 0.0f;
    #pragma unroll 8
    for (int d = ks * 128; d < ks * 128 + 128; d++)
        s = fmaf(srow[d], W3[(size_t)d * D_ + e], s);
    s += __shfl_xor_sync(0xffffffffu, s, 1);
    s += __shfl_xor_sync(0xffffffffu, s, 2);
    if (ks == 0) {
        __nv_bfloat16 h = __float2bfloat16(s);
        __nv_bfloat16 l = __float2bfloat16(s - __bfloat162float(h));
        g_v3h[i * D_ + e] = h;
        g_v3l[i * D_ + e] = l;
    }
    if (blockIdx.y == 0) {
        __shared__ float red[256];
        float p = 0.0f;
        for (int d = threadIdx.x; d < D_; d += 256) p = fmaf(b3[d], srow[d], p);
        red[threadIdx.x] = p;
        __syncthreads();
        for (int w = 128; w > 0; w >>= 1) {
            if (threadIdx.x < w) red[threadIdx.x] += red[threadIdx.x + w];
            __syncthreads();
        }
        if (threadIdx.x == 0) g_db[i] = red[0];
    }
}

// ---------------- pipelined bf16-split GEMM (MLP layers) -----------------------
// Tile 128x128, BK=32, 8 warps (64x32 each), 3-stage cp.async ring, ONE sync/slab.
// Stage (40960 B): Ahi@0, Alo@10240, Bhi@20480, Blo@30720; row stride 80B.
#define GSTAGE 40960
#define GSMEM  (3 * GSTAGE)
template<int RELU>
__global__ __launch_bounds__(256, 1)
void sc_pipe_gemm(const __nv_bfloat16* __restrict__ Ahi, const __nv_bfloat16* __restrict__ Alo,
                  const __nv_bfloat16* __restrict__ Bhi, const __nv_bfloat16* __restrict__ Blo,
                  const float* __restrict__ bias,
                  __nv_bfloat16* __restrict__ Chi, __nv_bfloat16* __restrict__ Clo) {
    extern __shared__ char sm[];
    const int tid = threadIdx.x;
    const int wid = tid >> 5, lane = tid & 31;
    const int wm = wid & 1, wn = wid >> 1;
    const int mbase = blockIdx.y * 128;
    const int nbase = blockIdx.x * 128;
    const uint32_t sb = smem_u32(sm);

    const __nv_bfloat16* Ah = Ahi + (size_t)mbase * D_;
    const __nv_bfloat16* Al = Alo + (size_t)mbase * D_;
    const __nv_bfloat16* Bh = Bhi + (size_t)nbase * D_;
    const __nv_bfloat16* Bl = Blo + (size_t)nbase * D_;

    const int idx0 = tid * 2;
    const int prow0 = idx0 >> 2,        pch0 = (idx0 & 3);
    const int prow1 = (idx0 + 1) >> 2,  pch1 = ((idx0 + 1) & 3);

    float brg[4][2];
    #pragma unroll
    for (int nf = 0; nf < 4; nf++) {
        int col = nbase + wn * 32 + nf * 8 + (lane & 3) * 2;
        brg[nf][0] = bias[col];
        brg[nf][1] = bias[col + 1];
    }

    float acc[4][4][4];
    #pragma unroll
    for (int a = 0; a < 4; a++)
        #pragma unroll
        for (int b = 0; b < 4; b++)
            #pragma unroll
            for (int c = 0; c < 4; c++) acc[a][b][c] = 0.0f;

    const uint32_t a_l = sb + (uint32_t)((wm * 64 + (lane & 15)) * 80 + (lane >> 4) * 16);
    const uint32_t b_l = sb + 20480u +
        (uint32_t)((wn * 32 + ((lane >> 4) & 1) * 8 + (lane & 7)) * 80 + ((lane >> 3) & 1) * 16);

    auto ISSUE = [&](int stage, int slab) {
        const int k0 = slab * 32;
        const uint32_t base = sb + (uint32_t)stage * GSTAGE;
        uint32_t d0 = base + (uint32_t)prow0 * 80u + (uint32_t)pch0 * 16u;
        uint32_t d1 = base + (uint32_t)prow1 * 80u + (uint32_t)pch1 * 16u;
        size_t s0 = (size_t)prow0 * D_ + k0 + pch0 * 8;
        size_t s1 = (size_t)prow1 * D_ + k0 + pch1 * 8;
        cp16(d0,          Ah + s0);  cp16(d1,          Ah + s1);
        cp16(d0 + 10240u, Al + s0);  cp16(d1 + 10240u, Al + s1);
        cp16(d0 + 20480u, Bh + s0);  cp16(d1 + 20480u, Bh + s1);
        cp16(d0 + 30720u, Bl + s0);  cp16(d1 + 30720u, Bl + s1);
        CP_COMMIT();
    };

    auto COMP = [&](int stage) {
        uint32_t ab  = a_l + (uint32_t)stage * GSTAGE;
        uint32_t bb_ = b_l + (uint32_t)stage * GSTAGE;
        #pragma unroll
        for (int ks = 0; ks < 2; ks++) {
            uint32_t ak = ab + ks * 32;
            uint32_t bk = bb_ + ks * 32;
            uint32_t af[4][4], b0[2][4], b1[2][4];
            #pragma unroll
            for (int mf = 0; mf < 4; mf++) ldsm_x4(af[mf], ak + mf * 1280);
            #pragma unroll
            for (int p = 0; p < 2; p++) ldsm_x4(b0[p], bk + p * 1280);
            #pragma unroll
            for (int mf = 0; mf < 4; mf++)
                #pragma unroll
                for (int nf = 0; nf < 4; nf++)
                    mma_bf16(acc[mf][nf], af[mf], &b0[nf >> 1][(nf & 1) * 2]);
            #pragma unroll
            for (int p = 0; p < 2; p++) ldsm_x4(b1[p], bk + 10240 + p * 1280);
            #pragma unroll
            for (int mf = 0; mf < 4; mf++)
                #pragma unroll
                for (int nf = 0; nf < 4; nf++)
                    mma_bf16(acc[mf][nf], af[mf], &b1[nf >> 1][(nf & 1) * 2]);
            #pragma unroll
            for (int mf = 0; mf < 4; mf++) ldsm_x4(af[mf], ak + 10240 + mf * 1280);
            #pragma unroll
            for (int mf = 0; mf < 4; mf++)
                #pragma unroll
                for (int nf = 0; nf < 4; nf++)
                    mma_bf16(acc[mf][nf], af[mf], &b0[nf >> 1][(nf & 1) * 2]);
        }
    };

    ISSUE(0, 0);
    ISSUE(1, 1);
    for (int i = 0; i < 16; i++) {
        if (i < 15) { CP_WAIT1(); } else { CP_WAIT0(); }
        __syncthreads();                 // covers cp.async visibility + stage reuse
        if (i < 14) ISSUE((i + 2) % 3, i + 2);
        COMP(i % 3);
    }

    #pragma unroll
    for (int mf = 0; mf < 4; mf++) {
        int row0 = mbase + wm * 64 + mf * 16 + (lane >> 2);
        #pragma unroll
        for (int nf = 0; nf < 4; nf++) {
            int col = nbase + wn * 32 + nf * 8 + (lane & 3) * 2;
            float2 v0, v1;
            v0.x = acc[mf][nf][0] + brg[nf][0];
            v0.y = acc[mf][nf][1] + brg[nf][1];
            v1.x = acc[mf][nf][2] + brg[nf][0];
            v1.y = acc[mf][nf][3] + brg[nf][1];
            if (RELU) {
                v0.x = fmaxf(v0.x, 0.f); v0.y = fmaxf(v0.y, 0.f);
                v1.x = fmaxf(v1.x, 0.f); v1.y = fmaxf(v1.y, 0.f);
            }
            __nv_bfloat16 h0 = __float2bfloat16(v0.x), h1 = __float2bfloat16(v0.y);
            __nv_bfloat16 h2 = __float2bfloat16(v1.x), h3 = __float2bfloat16(v1.y);
            __nv_bfloat16 l0 = __float2bfloat16(v0.x - __bfloat162float(h0));
            __nv_bfloat16 l1 = __float2bfloat16(v0.y - __bfloat162float(h1));
            __nv_bfloat16 l2 = __float2bfloat16(v1.x - __bfloat162float(h2));
            __nv_bfloat16 l3 = __float2bfloat16(v1.y - __bfloat162float(h3));
            *(uint32_t*)&Chi[(size_t)row0 * D_ + col]       = pack_bf16(h0, h1);
            *(uint32_t*)&Chi[(size_t)(row0 + 8) * D_ + col] = pack_bf16(h2, h3);
            *(uint32_t*)&Clo[(size_t)row0 * D_ + col]       = pack_bf16(l0, l1);
            *(uint32_t*)&Clo[(size_t)(row0 + 8) * D_ + col] = pack_bf16(l2, l3);
        }
    }
}

// ---------------- dots via mma ---------------------------------------------------
#define DSTAGE 30720
#define DSMEM  (2 * DSTAGE)
__global__ __launch_bounds__(256, 2)
void sc_dots_mma(const __nv_bfloat16* __restrict__ Ahi, const __nv_bfloat16* __restrict__ Alo) {
    extern __shared__ char sm[];
    const int tid = threadIdx.x;
    const int wid = tid >> 5, lane = tid & 31;
    const int mbase = blockIdx.x * 128;
    const uint32_t sb = smem_u32(sm);
    __shared__ float sdb[64];
    if (tid < 64) sdb[tid] = g_db[tid];

    const __nv_bfloat16* Ah = Ahi + (size_t)mbase * D_;
    const __nv_bfloat16* Al = Alo + (size_t)mbase * D_;

    const int prow = tid >> 1, pch0 = (tid & 1) * 2, pch1 = pch0 + 1;
    const int brow = tid >> 2, bch = tid & 3;

    float acc[8][4];
    #pragma unroll
    for (int u = 0; u < 8; u++)
        #pragma unroll
        for (int v = 0; v < 4; v++) acc[u][v] = 0.0f;

    const uint32_t a_l = sb + (uint32_t)((wid * 16 + (lane & 15)) * 80 + (lane >> 4) * 16);
    const uint32_t b_l = sb + 20480u +
        (uint32_t)((((lane >> 4) & 1) * 8 + (lane & 7)) * 80 + ((lane >> 3) & 1) * 16);

    auto ISSUE = [&](int stage, int slab) {
        const int k0 = slab * 32;
        const uint32_t base = sb + (uint32_t)stage * DSTAGE;
        uint32_t d0 = base + (uint32_t)prow * 80u + (uint32_t)pch0 * 16u;
        size_t s0 = (size_t)prow * D_ + k0 + pch0 * 8;
        size_t s1 = (size_t)prow * D_ + k0 + pch1 * 8;
        cp16(d0,          Ah + s0);  cp16(d0 + 16u,          Ah + s1);
        cp16(d0 + 10240u, Al + s0);  cp16(d0 + 10240u + 16u, Al + s1);
        uint32_t db_ = base + 20480u + (uint32_t)brow * 80u + (uint32_t)bch * 16u;
        size_t sB = (size_t)brow * D_ + k0 + bch * 8;
        cp16(db_,         g_v3h + sB);
        cp16(db_ + 5120u, g_v3l + sB);
        CP_COMMIT();
    };

    auto COMP = [&](int stage) {
        uint32_t ab  = a_l + (uint32_t)stage * DSTAGE;
        uint32_t bb_ = b_l + (uint32_t)stage * DSTAGE;
        #pragma unroll
        for (int ks = 0; ks < 2; ks++) {
            uint32_t ak = ab + ks * 32;
            uint32_t bk = bb_ + ks * 32;
            uint32_t af[4], bh[4][4], bl[4][4];
            ldsm_x4(af, ak);
            #pragma unroll
            for (int p = 0; p < 4; p++) ldsm_x4(bh[p], bk + p * 1280);
            #pragma unroll
            for (int nf = 0; nf < 8; nf++)
                mma_bf16(acc[nf], af, &bh[nf >> 1][(nf & 1) * 2]);
            #pragma unroll
            for (int p = 0; p < 4; p++) ldsm_x4(bl[p], bk + 5120 + p * 1280);
            #pragma unroll
            for (int nf = 0; nf < 8; nf++)
                mma_bf16(acc[nf], af, &bl[nf >> 1][(nf & 1) * 2]);
            ldsm_x4(af, ak + 10240);
            #pragma unroll
            for (int nf = 0; nf < 8; nf++)
                mma_bf16(acc[nf], af, &bh[nf >> 1][(nf & 1) * 2]);
        }
    };

    ISSUE(0, 0);
    ISSUE(1, 1);
    for (int i = 0; i < 16; i++) {
        if (i < 15) { CP_WAIT1(); } else { CP_WAIT0(); }
        __syncthreads();
        COMP(i & 1);
        __syncthreads();
        if (i < 14) ISSUE(i & 1, i + 2);
    }

    const float scale = 0.04419417382415922f;
    const int b  = mbase / N_;
    const int jb = mbase % N_;
    const int r0 = jb + wid * 16 + (lane >> 2);
    #pragma unroll
    for (int nf = 0; nf < 8; nf++) {
        int col = nf * 8 + (lane & 3) * 2;
        float dbx = sdb[col], dby = sdb[col + 1];
        float2 v0, v1;
        v0.x = (acc[nf][0] + dbx) * scale;
        v0.y = (acc[nf][1] + dby) * scale;
        v1.x = (acc[nf][2] + dbx) * scale;
        v1.y = (acc[nf][3] + dby) * scale;
        *(float2*)&g_dots[((size_t)b * N_ + r0) * SPAD + col]     = v0;
        *(float2*)&g_dots[((size_t)b * N_ + r0 + 8) * SPAD + col] = v1;
    }
}

// ---------------- rowsum + total ---------------------------------------------
__global__ __launch_bounds__(256)
void sc_rowsum_kernel() {
    int b = blockIdx.x;
    int i = threadIdx.x & 63;
    int q = threadIdx.x >> 6;
    __shared__ float red[4][64];
    __shared__ float tot[64];
    float s = 0.0f;
    for (int j = q * 256; j < q * 256 + 256; j++)
        s += g_dots[((size_t)b * N_ + j) * SPAD + i];
    red[q][i] = s;
    __syncthreads();
    if (threadIdx.x < 64) {
        float r = red[0][threadIdx.x] + red[1][threadIdx.x] +
                  red[2][threadIdx.x] + red[3][threadIdx.x];
        if (threadIdx.x < S_) g_rowsum[b * S_ + threadIdx.x] = r;
        tot[threadIdx.x] = (threadIdx.x < S_) ? r : 0.0f;
    }
    __syncthreads();
    if (threadIdx.x < 32) {
        float t = tot[threadIdx.x] + tot[threadIdx.x + 32];
        #pragma unroll
        for (int w = 16; w > 0; w >>= 1) t += __shfl_down_sync(0xffffffffu, t, w);
        if (threadIdx.x == 0) g_total[b] = t;
    }
}

// ---------------- softmax (also emits attn hi/lo bf16) --------------------------
__global__ __launch_bounds__(128)
void sc_softmax_kernel(float* __restrict__ attn_out) {
    int b = blockIdx.y;
    int j = blockIdx.x * 128 + threadIdx.x;
    __shared__ float inv_rs[S_];
    if (threadIdx.x < S_) inv_rs[threadIdx.x] = 1.0f / g_rowsum[b * S_ + threadIdx.x];
    __syncthreads();
    float tot = g_total[b];
    const float* src = &g_dots[((size_t)b * N_ + j) * SPAD];
    float dn[S_];
    float m = -INFINITY;
    #pragma unroll
    for (int i = 0; i < S_; i++) {
        float v = src[i] * inv_rs[i] * tot;
        dn[i] = v;
        m = fmaxf(m, v);
    }
    float s = 0.f;
    #pragma unroll
    for (int i = 0; i < S_; i++) s += expf(dn[i] - m);
    float inv_s = 1.0f / s;
    #pragma unroll
    for (int i = 0; i < S_; i++) {
        float sm  = expf(dn[i] - m) * inv_s;
        float sig = 1.0f / (1.0f + expf(-dn[i]));
        float a = sm * sig;
        attn_out[((size_t)b * S_ + i) * N_ + j] = a;
        __nv_bfloat16 h = __float2bfloat16(a);
        __nv_bfloat16 l = __float2bfloat16(a - __bfloat162float(h));
        g_ath[((size_t)b * 64 + i) * N_ + j] = h;
        g_atl[((size_t)b * 64 + i) * N_ + j] = l;
    }
}

// ---------------- updates via mma -----------------------------------------------
#define USTAGE 27648
#define USMEM  (2 * USTAGE)
__global__ __launch_bounds__(256, 2)
void sc_updates_mma(const float* __restrict__ inputs, float* __restrict__ out) {
    extern __shared__ char sm[];
    const int tid = threadIdx.x;
    const int wid = tid >> 5, lane = tid & 31;
    const int wm = wid & 1, wn = wid >> 1;
    const int b = blockIdx.y;
    const int dtile = blockIdx.x * 128;
    const uint32_t sb = smem_u32(sm);

    const __nv_bfloat16* Ah = g_ath + (size_t)b * 64 * N_;
    const __nv_bfloat16* Al = g_atl + (size_t)b * 64 * N_;
    const float* Bsrc = inputs + (size_t)b * N_ * D_ + dtile;

    const int arow = tid >> 2, ach = tid & 3;
    const int brow = tid >> 3, bdc = (tid & 7) * 16;

    float acc[2][4][4];
    #pragma unroll
    for (int a = 0; a < 2; a++)
        #pragma unroll
        for (int c = 0; c < 4; c++)
            #pragma unroll
            for (int e = 0; e < 4; e++) acc[a][c][e] = 0.0f;

    const uint32_t a_l = sb + (uint32_t)((wm * 32 + (lane & 15)) * 80 + (lane >> 4) * 16);
    const uint32_t b_l = sb + 10240u +
        (uint32_t)((((lane >> 3) & 1) * 8 + (lane & 7)) * 272 +
                   (wn * 32 + (lane >> 4) * 8) * 2);

    auto ISSUE_A = [&](int stage, int slab) {
        const uint32_t base = sb + (uint32_t)stage * USTAGE;
        uint32_t d0 = base + (uint32_t)arow * 80u + (uint32_t)ach * 16u;
        size_t s0 = (size_t)arow * N_ + slab * 32 + ach * 8;
        cp16(d0,         Ah + s0);
        cp16(d0 + 5120u, Al + s0);
        CP_COMMIT();
    };

    float4 breg[2][4];
    auto LDGB = [&](int slab, int buf) {
        const float* p = Bsrc + (size_t)(slab * 32 + brow) * D_ + bdc;
        #pragma unroll
        for (int q = 0; q < 4; q++) breg[buf][q] = *(const float4*)(p + q * 4);
    };
    auto STSB = [&](int stage, int buf) {
        const uint32_t base = sb + (uint32_t)stage * USTAGE + 10240u +
                              (uint32_t)brow * 272u + (uint32_t)bdc * 2u;
        #pragma unroll
        for (int q = 0; q < 4; q++) {
            uint2 h, l;
            split4(breg[buf][q], h, l);
            *(uint2*)(sm + (base - sb) + q * 8)         = h;
            *(uint2*)(sm + (base - sb) + 8704u + q * 8) = l;
        }
    };

    auto COMP = [&](int stage) {
        uint32_t ab  = a_l + (uint32_t)stage * USTAGE;
        uint32_t bb_ = b_l + (uint32_t)stage * USTAGE;
        #pragma unroll
        for (int ks = 0; ks < 2; ks++) {
            uint32_t ak = ab + ks * 32;
            uint32_t bk = bb_ + ks * 16 * 272;
            uint32_t af[2][4], bh[2][4], bl[2][4];
            #pragma unroll
            for (int mf = 0; mf < 2; mf++) ldsm_x4(af[mf], ak + mf * 1280);
            #pragma unroll
            for (int p = 0; p < 2; p++) ldsm_x4_t(bh[p], bk + p * 32);
            #pragma unroll
            for (int mf = 0; mf < 2; mf++)
                #pragma unroll
                for (int nf = 0; nf < 4; nf++)
                    mma_bf16(acc[mf][nf], af[mf], &bh[nf >> 1][(nf & 1) * 2]);
            #pragma unroll
            for (int p = 0; p < 2; p++) ldsm_x4_t(bl[p], bk + 8704u + p * 32);
            #pragma unroll
            for (int mf = 0; mf < 2; mf++)
                #pragma unroll
                for (int nf = 0; nf < 4; nf++)
                    mma_bf16(acc[mf][nf], af[mf], &bl[nf >> 1][(nf & 1) * 2]);
            #pragma unroll
            for (int mf = 0; mf < 2; mf++) ldsm_x4(af[mf], ak + 5120u + mf * 1280);
            #pragma unroll
            for (int mf = 0; mf < 2; mf++)
                #pragma unroll
                for (int nf = 0; nf < 4; nf++)
                    mma_bf16(acc[mf][nf], af[mf], &bh[nf >> 1][(nf & 1) * 2]);
        }
    };

    LDGB(0, 0);
    ISSUE_A(0, 0);
    ISSUE_A(1, 1);
    for (int i = 0; i < 32; i++) {
        const int s = i & 1;
        if (i < 31) LDGB(i + 1, s ^ 1);
        if (i < 31) { CP_WAIT1(); } else { CP_WAIT0(); }
        __syncthreads();
        STSB(s, s);
        __syncthreads();
        COMP(s);
        __syncthreads();
        if (i < 30) ISSUE_A(s, i + 2);
    }

    const float invd = 1.0f / (float)D_;
    #pragma unroll
    for (int mf = 0; mf < 2; mf++) {
        int i0 = wm * 32 + mf * 16 + (lane >> 2);
        #pragma unroll
        for (int nf = 0; nf < 4; nf++) {
            int col = dtile + wn * 32 + nf * 8 + (lane & 3) * 2;
            if (i0 < S_) {
                float2 v;
                v.x = acc[mf][nf][0] * invd;
                v.y = acc[mf][nf][1] * invd;
                *(float2*)&out[((size_t)b * S_ + i0) * D_ + col] = v;
            }
            if (i0 + 8 < S_) {
                float2 v;
                v.x = acc[mf][nf][2] * invd;
                v.y = acc[mf][nf][3] * invd;
                *(float2*)&out[((size_t)b * S_ + i0 + 8) * D_ + col] = v;
            }
        }
    }
}

// ---------------- launch ---------------------------------------------------------
extern "C" void kernel_launch(void* const* d_in, const int* in_sizes, int n_in,
                              void* d_out, int out_size) {
    const float* inputs_pe = (const float*)d_in[0];
    const float* inputs    = (const float*)d_in[1];
    const float* slots     = (const float*)d_in[2];
    const float* W1 = (const float*)d_in[3];
    const float* b1 = (const float*)d_in[4];
    const float* W2 = (const float*)d_in[5];
    const float* b2 = (const float*)d_in[6];
    const float* W3 = (const float*)d_in[7];
    const float* b3 = (const float*)d_in[8];
    float* out = (float*)d_out;

    __nv_bfloat16 *p0h, *p0l, *p1h, *p1l, *wh, *wl;
    float *attn_fb;
    cudaGetSymbolAddress((void**)&p0h, g_p0h);
    cudaGetSymbolAddress((void**)&p0l, g_p0l);
    cudaGetSymbolAddress((void**)&p1h, g_p1h);
    cudaGetSymbolAddress((void**)&p1l, g_p1l);
    cudaGetSymbolAddress((void**)&wh,  g_wh);
    cudaGetSymbolAddress((void**)&wl,  g_wl);
    cudaGetSymbolAddress((void**)&attn_fb, g_attn_fb);

    const size_t updates_elems = (size_t)B_ * S_ * D_;
    const size_t attn_elems    = (size_t)B_ * S_ * N_;
    float* attn_ptr = out + updates_elems;
    if ((size_t)out_size < updates_elems + attn_elems) attn_ptr = attn_fb;

    cudaFuncSetAttribute(sc_pipe_gemm<1>, cudaFuncAttributeMaxDynamicSharedMemorySize, GSMEM);
    cudaFuncSetAttribute(sc_dots_mma,     cudaFuncAttributeMaxDynamicSharedMemorySize, DSMEM);
    cudaFuncSetAttribute(sc_updates_mma,  cudaFuncAttributeMaxDynamicSharedMemorySize, USMEM);

    {
        int n4 = (M_ * D_) / 4;
        sc_split_kernel<<<(n4 + 255) / 256, 256>>>(inputs_pe, p0h, p0l, n4);
        int w4 = (D_ * D_) / 4;
        sc_split_kernel<<<(w4 + 255) / 256, 256>>>(W1, wh + 0 * D_ * D_, wl + 0 * D_ * D_, w4);
        sc_split_kernel<<<(w4 + 255) / 256, 256>>>(W2, wh + 1 * D_ * D_, wl + 1 * D_ * D_, w4);
    }
    {
        dim3 gv3(64, 8);
        sc_v3_kernel<<<gv3, 256>>>(slots, W3, b3);
    }

    dim3 gg(D_ / 128, M_ / 128);
    sc_pipe_gemm<1><<<gg, 256, GSMEM>>>(p0h, p0l, wh + 0 * D_ * D_, wl + 0 * D_ * D_, b1,
                                        p1h, p1l);
    sc_pipe_gemm<1><<<gg, 256, GSMEM>>>(p1h, p1l, wh + 1 * D_ * D_, wl + 1 * D_ * D_, b2,
                                        p0h, p0l);

    sc_dots_mma<<<M_ / 128, 256, DSMEM>>>(p0h, p0l);
    sc_rowsum_kernel<<<B_, 256>>>();

    dim3 gsm(N_ / 128, B_);
    sc_softmax_kernel<<<gsm, 128>>>(attn_ptr);

    dim3 gup(D_ / 128, B_);
    sc_updates_mma<<<gup, 256, USMEM>>>(inputs, out);
}

// round 13
// speedup vs baseline: 1.1930x; 1.1323x over previous
#include <cuda_runtime.h>
#include <cuda_bf16.h>
#include <math.h>
#include <stdint.h>

#define B_ 128
#define N_ 1024
#define D_ 512
#define S_ 50
#define M_ (B_ * N_)   // 131072
#define SPAD 64

// ---------------- scratch ----------------------------------------------------
__device__ __nv_bfloat16 g_p0h[(size_t)M_ * D_];
__device__ __nv_bfloat16 g_p0l[(size_t)M_ * D_];
__device__ __nv_bfloat16 g_p1h[(size_t)M_ * D_];
__device__ __nv_bfloat16 g_p1l[(size_t)M_ * D_];
__device__ __nv_bfloat16 g_wh[2][D_ * D_];
__device__ __nv_bfloat16 g_wl[2][D_ * D_];
__device__ __nv_bfloat16 g_v3h[64 * D_];
__device__ __nv_bfloat16 g_v3l[64 * D_];
__device__ float g_db[64];
__device__ float g_dots[(size_t)B_ * N_ * SPAD];
__device__ float g_rowsum[B_ * 64];
__device__ float g_attn_fb[(size_t)B_ * S_ * N_];
__device__ __nv_bfloat16 g_ath[(size_t)B_ * 64 * N_];
__device__ __nv_bfloat16 g_atl[(size_t)B_ * 64 * N_];

// ---------------- helpers ----------------------------------------------------
__device__ __forceinline__ uint32_t smem_u32(const void* p) {
    uint32_t a;
    asm("{ .reg .u64 t; cvta.to.shared.u64 t, %1; cvt.u32.u64 %0, t; }" : "=r"(a) : "l"(p));
    return a;
}
__device__ __forceinline__ void ldsm_x4(uint32_t* r, uint32_t addr) {
    asm volatile("ldmatrix.sync.aligned.m8n8.x4.shared.b16 {%0,%1,%2,%3}, [%4];"
                 : "=r"(r[0]), "=r"(r[1]), "=r"(r[2]), "=r"(r[3]) : "r"(addr));
}
__device__ __forceinline__ void ldsm_x4_t(uint32_t* r, uint32_t addr) {
    asm volatile("ldmatrix.sync.aligned.m8n8.x4.trans.shared.b16 {%0,%1,%2,%3}, [%4];"
                 : "=r"(r[0]), "=r"(r[1]), "=r"(r[2]), "=r"(r[3]) : "r"(addr));
}
__device__ __forceinline__ void mma_bf16(float* d, const uint32_t* a, const uint32_t* b) {
    asm volatile("mma.sync.aligned.m16n8k16.row.col.f32.bf16.bf16.f32 "
                 "{%0,%1,%2,%3},{%4,%5,%6,%7},{%8,%9},{%0,%1,%2,%3};"
                 : "+f"(d[0]), "+f"(d[1]), "+f"(d[2]), "+f"(d[3])
                 : "r"(a[0]), "r"(a[1]), "r"(a[2]), "r"(a[3]), "r"(b[0]), "r"(b[1]));
}
__device__ __forceinline__ void cp16(uint32_t dst, const void* src) {
    asm volatile("cp.async.cg.shared.global [%0], [%1], 16;" :: "r"(dst), "l"(src));
}
#define CP_COMMIT() asm volatile("cp.async.commit_group;" ::: "memory")
#define CP_WAIT1()  asm volatile("cp.async.wait_group 1;" ::: "memory")
#define CP_WAIT0()  asm volatile("cp.async.wait_group 0;" ::: "memory")

__device__ __forceinline__ uint32_t pack_bf16(__nv_bfloat16 a, __nv_bfloat16 b) {
    __nv_bfloat162 t = __halves2bfloat162(a, b);
    return *reinterpret_cast<uint32_t*>(&t);
}
__device__ __forceinline__ void split4(float4 v, uint2& hi, uint2& lo) {
    __nv_bfloat16 hx = __float2bfloat16(v.x), hy = __float2bfloat16(v.y);
    __nv_bfloat16 hz = __float2bfloat16(v.z), hw = __float2bfloat16(v.w);
    __nv_bfloat16 lx = __float2bfloat16(v.x - __bfloat162float(hx));
    __nv_bfloat16 ly = __float2bfloat16(v.y - __bfloat162float(hy));
    __nv_bfloat16 lz = __float2bfloat16(v.z - __bfloat162float(hz));
    __nv_bfloat16 lw = __float2bfloat16(v.w - __bfloat162float(hw));
    hi = make_uint2(pack_bf16(hx, hy), pack_bf16(hz, hw));
    lo = make_uint2(pack_bf16(lx, ly), pack_bf16(lz, lw));
}

// ---------------- misc small kernels ------------------------------------------
__global__ void sc_zero_kernel() {
    int i = blockIdx.x * blockDim.x + threadIdx.x;
    if (i < B_ * 64) g_rowsum[i] = 0.0f;
}
__global__ void sc_split_kernel(const float* __restrict__ src, __nv_bfloat16* __restrict__ hi,
                                __nv_bfloat16* __restrict__ lo, int n4) {
    int i = blockIdx.x * blockDim.x + threadIdx.x;
    if (i < n4) {
        float4 v = ((const float4*)src)[i];
        uint2 h, l;
        split4(v, h, l);
        ((uint2*)hi)[i] = h;
        ((uint2*)lo)[i] = l;
    }
}

// V3[i,:] = slots[i,:] @ W3 (bf16 hi/lo); db[i] = b3 . slots[i]
__global__ __launch_bounds__(256)
void sc_v3_kernel(const float* __restrict__ slots, const float* __restrict__ W3,
                  const float* __restrict__ b3) {
    int i = blockIdx.x;
    int ebase = blockIdx.y * 64;
    __shared__ float srow[D_];
    for (int d = threadIdx.x; d < D_; d += 256)
        srow[d] = (i < S_) ? slots[i * D_ + d] : 0.0f;
    __syncthreads();
    int el = threadIdx.x >> 2, ks = threadIdx.x & 3;
    int e = ebase + el;
    float s = 0.0f;
    #pragma unroll 8
    for (int d = ks * 128; d < ks * 128 + 128; d++)
        s = fmaf(srow[d], W3[(size_t)d * D_ + e], s);
    s += __shfl_xor_sync(0xffffffffu, s, 1);
    s += __shfl_xor_sync(0xffffffffu, s, 2);
    if (ks == 0) {
        __nv_bfloat16 h = __float2bfloat16(s);
        __nv_bfloat16 l = __float2bfloat16(s - __bfloat162float(h));
        g_v3h[i * D_ + e] = h;
        g_v3l[i * D_ + e] = l;
    }
    if (blockIdx.y == 0) {
        __shared__ float red[256];
        float p = 0.0f;
        for (int d = threadIdx.x; d < D_; d += 256) p = fmaf(b3[d], srow[d], p);
        red[threadIdx.x] = p;
        __syncthreads();
        for (int w = 128; w > 0; w >>= 1) {
            if (threadIdx.x < w) red[threadIdx.x] += red[threadIdx.x + w];
            __syncthreads();
        }
        if (threadIdx.x == 0) g_db[i] = red[0];
    }
}

// ---------------- pipelined bf16-split GEMM (round-10 geometry) ----------------
// Tile 128x128, BK=32, 256 thr / 8 warps (64x32 each), 2-stage cp.async, 2 CTAs/SM.
#define GSTAGE 40960
#define GSMEM  (2 * GSTAGE)
template<int RELU>
__global__ __launch_bounds__(256, 2)
void sc_pipe_gemm(const __nv_bfloat16* __restrict__ Ahi, const __nv_bfloat16* __restrict__ Alo,
                  const __nv_bfloat16* __restrict__ Bhi, const __nv_bfloat16* __restrict__ Blo,
                  const float* __restrict__ bias,
                  __nv_bfloat16* __restrict__ Chi, __nv_bfloat16* __restrict__ Clo) {
    extern __shared__ char sm[];
    const int tid = threadIdx.x;
    const int wid = tid >> 5, lane = tid & 31;
    const int wm = wid & 1, wn = wid >> 1;
    const int mbase = blockIdx.y * 128;
    const int nbase = blockIdx.x * 128;
    const uint32_t sb = smem_u32(sm);

    const __nv_bfloat16* Ah = Ahi + (size_t)mbase * D_;
    const __nv_bfloat16* Al = Alo + (size_t)mbase * D_;
    const __nv_bfloat16* Bh = Bhi + (size_t)nbase * D_;
    const __nv_bfloat16* Bl = Blo + (size_t)nbase * D_;

    const int idx0 = tid * 2;
    const int prow0 = idx0 >> 2,        pch0 = (idx0 & 3);
    const int prow1 = (idx0 + 1) >> 2,  pch1 = ((idx0 + 1) & 3);

    float brg[4][2];
    #pragma unroll
    for (int nf = 0; nf < 4; nf++) {
        int col = nbase + wn * 32 + nf * 8 + (lane & 3) * 2;
        brg[nf][0] = bias[col];
        brg[nf][1] = bias[col + 1];
    }

    float acc[4][4][4];
    #pragma unroll
    for (int a = 0; a < 4; a++)
        #pragma unroll
        for (int b = 0; b < 4; b++)
            #pragma unroll
            for (int c = 0; c < 4; c++) acc[a][b][c] = 0.0f;

    const uint32_t a_l = sb + (uint32_t)((wm * 64 + (lane & 15)) * 80 + (lane >> 4) * 16);
    const uint32_t b_l = sb + 20480u +
        (uint32_t)((wn * 32 + ((lane >> 4) & 1) * 8 + (lane & 7)) * 80 + ((lane >> 3) & 1) * 16);

    auto ISSUE = [&](int stage, int slab) {
        const int k0 = slab * 32;
        const uint32_t base = sb + (uint32_t)stage * GSTAGE;
        uint32_t d0 = base + (uint32_t)prow0 * 80u + (uint32_t)pch0 * 16u;
        uint32_t d1 = base + (uint32_t)prow1 * 80u + (uint32_t)pch1 * 16u;
        size_t s0 = (size_t)prow0 * D_ + k0 + pch0 * 8;
        size_t s1 = (size_t)prow1 * D_ + k0 + pch1 * 8;
        cp16(d0,          Ah + s0);  cp16(d1,          Ah + s1);
        cp16(d0 + 10240u, Al + s0);  cp16(d1 + 10240u, Al + s1);
        cp16(d0 + 20480u, Bh + s0);  cp16(d1 + 20480u, Bh + s1);
        cp16(d0 + 30720u, Bl + s0);  cp16(d1 + 30720u, Bl + s1);
        CP_COMMIT();
    };

    auto COMP = [&](int stage) {
        uint32_t ab  = a_l + (uint32_t)stage * GSTAGE;
        uint32_t bb_ = b_l + (uint32_t)stage * GSTAGE;
        #pragma unroll
        for (int ks = 0; ks < 2; ks++) {
            uint32_t ak = ab + ks * 32;
            uint32_t bk = bb_ + ks * 32;
            uint32_t af[4][4], b0[2][4], b1[2][4];
            #pragma unroll
            for (int mf = 0; mf < 4; mf++) ldsm_x4(af[mf], ak + mf * 1280);
            #pragma unroll
            for (int p = 0; p < 2; p++) ldsm_x4(b0[p], bk + p * 1280);
            #pragma unroll
            for (int mf = 0; mf < 4; mf++)
                #pragma unroll
                for (int nf = 0; nf < 4; nf++)
                    mma_bf16(acc[mf][nf], af[mf], &b0[nf >> 1][(nf & 1) * 2]);
            #pragma unroll
            for (int p = 0; p < 2; p++) ldsm_x4(b1[p], bk + 10240 + p * 1280);
            #pragma unroll
            for (int mf = 0; mf < 4; mf++)
                #pragma unroll
                for (int nf = 0; nf < 4; nf++)
                    mma_bf16(acc[mf][nf], af[mf], &b1[nf >> 1][(nf & 1) * 2]);
            #pragma unroll
            for (int mf = 0; mf < 4; mf++) ldsm_x4(af[mf], ak + 10240 + mf * 1280);
            #pragma unroll
            for (int mf = 0; mf < 4; mf++)
                #pragma unroll
                for (int nf = 0; nf < 4; nf++)
                    mma_bf16(acc[mf][nf], af[mf], &b0[nf >> 1][(nf & 1) * 2]);
        }
    };

    ISSUE(0, 0);
    ISSUE(1, 1);
    for (int i = 0; i < 16; i++) {
        if (i < 15) { CP_WAIT1(); } else { CP_WAIT0(); }
        __syncthreads();
        COMP(i & 1);
        __syncthreads();
        if (i < 14) ISSUE(i & 1, i + 2);
    }

    #pragma unroll
    for (int mf = 0; mf < 4; mf++) {
        int row0 = mbase + wm * 64 + mf * 16 + (lane >> 2);
        #pragma unroll
        for (int nf = 0; nf < 4; nf++) {
            int col = nbase + wn * 32 + nf * 8 + (lane & 3) * 2;
            float2 v0, v1;
            v0.x = acc[mf][nf][0] + brg[nf][0];
            v0.y = acc[mf][nf][1] + brg[nf][1];
            v1.x = acc[mf][nf][2] + brg[nf][0];
            v1.y = acc[mf][nf][3] + brg[nf][1];
            if (RELU) {
                v0.x = fmaxf(v0.x, 0.f); v0.y = fmaxf(v0.y, 0.f);
                v1.x = fmaxf(v1.x, 0.f); v1.y = fmaxf(v1.y, 0.f);
            }
            __nv_bfloat16 h0 = __float2bfloat16(v0.x), h1 = __float2bfloat16(v0.y);
            __nv_bfloat16 h2 = __float2bfloat16(v1.x), h3 = __float2bfloat16(v1.y);
            __nv_bfloat16 l0 = __float2bfloat16(v0.x - __bfloat162float(h0));
            __nv_bfloat16 l1 = __float2bfloat16(v0.y - __bfloat162float(h1));
            __nv_bfloat16 l2 = __float2bfloat16(v1.x - __bfloat162float(h2));
            __nv_bfloat16 l3 = __float2bfloat16(v1.y - __bfloat162float(h3));
            *(uint32_t*)&Chi[(size_t)row0 * D_ + col]       = pack_bf16(h0, h1);
            *(uint32_t*)&Chi[(size_t)(row0 + 8) * D_ + col] = pack_bf16(h2, h3);
            *(uint32_t*)&Clo[(size_t)row0 * D_ + col]       = pack_bf16(l0, l1);
            *(uint32_t*)&Clo[(size_t)(row0 + 8) * D_ + col] = pack_bf16(l2, l3);
        }
    }
}

// ---------------- dots via mma + fused rowsum ----------------------------------
#define DSTAGE 30720
#define DSMEM  (2 * DSTAGE)
__global__ __launch_bounds__(256, 2)
void sc_dots_mma(const __nv_bfloat16* __restrict__ Ahi, const __nv_bfloat16* __restrict__ Alo) {
    extern __shared__ char sm[];
    const int tid = threadIdx.x;
    const int wid = tid >> 5, lane = tid & 31;
    const int mbase = blockIdx.x * 128;
    const uint32_t sb = smem_u32(sm);
    __shared__ float sdb[64];
    __shared__ float rsum[8][64];
    if (tid < 64) sdb[tid] = g_db[tid];

    const __nv_bfloat16* Ah = Ahi + (size_t)mbase * D_;
    const __nv_bfloat16* Al = Alo + (size_t)mbase * D_;

    const int prow = tid >> 1, pch0 = (tid & 1) * 2, pch1 = pch0 + 1;
    const int brow = tid >> 2, bch = tid & 3;

    float acc[8][4];
    #pragma unroll
    for (int u = 0; u < 8; u++)
        #pragma unroll
        for (int v = 0; v < 4; v++) acc[u][v] = 0.0f;

    const uint32_t a_l = sb + (uint32_t)((wid * 16 + (lane & 15)) * 80 + (lane >> 4) * 16);
    const uint32_t b_l = sb + 20480u +
        (uint32_t)((((lane >> 4) & 1) * 8 + (lane & 7)) * 80 + ((lane >> 3) & 1) * 16);

    auto ISSUE = [&](int stage, int slab) {
        const int k0 = slab * 32;
        const uint32_t base = sb + (uint32_t)stage * DSTAGE;
        uint32_t d0 = base + (uint32_t)prow * 80u + (uint32_t)pch0 * 16u;
        size_t s0 = (size_t)prow * D_ + k0 + pch0 * 8;
        size_t s1 = (size_t)prow * D_ + k0 + pch1 * 8;
        cp16(d0,          Ah + s0);  cp16(d0 + 16u,          Ah + s1);
        cp16(d0 + 10240u, Al + s0);  cp16(d0 + 10240u + 16u, Al + s1);
        uint32_t db_ = base + 20480u + (uint32_t)brow * 80u + (uint32_t)bch * 16u;
        size_t sB = (size_t)brow * D_ + k0 + bch * 8;
        cp16(db_,         g_v3h + sB);
        cp16(db_ + 5120u, g_v3l + sB);
        CP_COMMIT();
    };

    auto COMP = [&](int stage) {
        uint32_t ab  = a_l + (uint32_t)stage * DSTAGE;
        uint32_t bb_ = b_l + (uint32_t)stage * DSTAGE;
        #pragma unroll
        for (int ks = 0; ks < 2; ks++) {
            uint32_t ak = ab + ks * 32;
            uint32_t bk = bb_ + ks * 32;
            uint32_t af[4], bh[4][4], bl[4][4];
            ldsm_x4(af, ak);
            #pragma unroll
            for (int p = 0; p < 4; p++) ldsm_x4(bh[p], bk + p * 1280);
            #pragma unroll
            for (int nf = 0; nf < 8; nf++)
                mma_bf16(acc[nf], af, &bh[nf >> 1][(nf & 1) * 2]);
            #pragma unroll
            for (int p = 0; p < 4; p++) ldsm_x4(bl[p], bk + 5120 + p * 1280);
            #pragma unroll
            for (int nf = 0; nf < 8; nf++)
                mma_bf16(acc[nf], af, &bl[nf >> 1][(nf & 1) * 2]);
            ldsm_x4(af, ak + 10240);
            #pragma unroll
            for (int nf = 0; nf < 8; nf++)
                mma_bf16(acc[nf], af, &bh[nf >> 1][(nf & 1) * 2]);
        }
    };

    ISSUE(0, 0);
    ISSUE(1, 1);
    for (int i = 0; i < 16; i++) {
        if (i < 15) { CP_WAIT1(); } else { CP_WAIT0(); }
        __syncthreads();
        COMP(i & 1);
        __syncthreads();
        if (i < 14) ISSUE(i & 1, i + 2);
    }

    const float scale = 0.04419417382415922f;
    const int b  = mbase / N_;
    const int jb = mbase % N_;
    const int r0 = jb + wid * 16 + (lane >> 2);
    #pragma unroll
    for (int nf = 0; nf < 8; nf++) {
        int col = nf * 8 + (lane & 3) * 2;
        float dbx = sdb[col], dby = sdb[col + 1];
        float2 v0, v1;
        v0.x = (acc[nf][0] + dbx) * scale;
        v0.y = (acc[nf][1] + dby) * scale;
        v1.x = (acc[nf][2] + dbx) * scale;
        v1.y = (acc[nf][3] + dby) * scale;
        *(float2*)&g_dots[((size_t)b * N_ + r0) * SPAD + col]     = v0;
        *(float2*)&g_dots[((size_t)b * N_ + r0 + 8) * SPAD + col] = v1;
        // fused rowsum partials: sum over this warp's 16 rows via shfl tree
        float s0 = v0.x + v1.x;
        float s1 = v0.y + v1.y;
        #pragma unroll
        for (int off = 4; off < 32; off <<= 1) {
            s0 += __shfl_down_sync(0xffffffffu, s0, off);
            s1 += __shfl_down_sync(0xffffffffu, s1, off);
        }
        if (lane < 4) {
            rsum[wid][nf * 8 + lane * 2]     = s0;
            rsum[wid][nf * 8 + lane * 2 + 1] = s1;
        }
    }
    __syncthreads();
    if (tid < 64) {
        float t = 0.0f;
        #pragma unroll
        for (int w = 0; w < 8; w++) t += rsum[w][tid];
        atomicAdd(&g_rowsum[b * 64 + tid], t);
    }
}

// ---------------- softmax (computes total in-block; emits attn f32 + hi/lo) ----
__global__ __launch_bounds__(128)
void sc_softmax_kernel(float* __restrict__ attn_out) {
    int b = blockIdx.y;
    int j = blockIdx.x * 128 + threadIdx.x;
    __shared__ float inv_rs[S_];
    __shared__ float rs_raw[S_];
    if (threadIdx.x < S_) {
        float r = g_rowsum[b * 64 + threadIdx.x];
        rs_raw[threadIdx.x] = r;
        inv_rs[threadIdx.x] = 1.0f / r;
    }
    __syncthreads();
    float tot = 0.0f;
    #pragma unroll
    for (int i = 0; i < S_; i++) tot += rs_raw[i];
    const float* src = &g_dots[((size_t)b * N_ + j) * SPAD];
    float dn[S_];
    float m = -INFINITY;
    #pragma unroll
    for (int i = 0; i < S_; i++) {
        float v = src[i] * inv_rs[i] * tot;
        dn[i] = v;
        m = fmaxf(m, v);
    }
    float s = 0.f;
    #pragma unroll
    for (int i = 0; i < S_; i++) s += expf(dn[i] - m);
    float inv_s = 1.0f / s;
    #pragma unroll
    for (int i = 0; i < S_; i++) {
        float sm  = expf(dn[i] - m) * inv_s;
        float sig = 1.0f / (1.0f + expf(-dn[i]));
        float a = sm * sig;
        attn_out[((size_t)b * S_ + i) * N_ + j] = a;
        __nv_bfloat16 h = __float2bfloat16(a);
        __nv_bfloat16 l = __float2bfloat16(a - __bfloat162float(h));
        g_ath[((size_t)b * 64 + i) * N_ + j] = h;
        g_atl[((size_t)b * 64 + i) * N_ + j] = l;
    }
}

// ---------------- updates via mma -----------------------------------------------
#define USTAGE 27648
#define USMEM  (2 * USTAGE)
__global__ __launch_bounds__(256, 2)
void sc_updates_mma(const float* __restrict__ inputs, float* __restrict__ out) {
    extern __shared__ char sm[];
    const int tid = threadIdx.x;
    const int wid = tid >> 5, lane = tid & 31;
    const int wm = wid & 1, wn = wid >> 1;
    const int b = blockIdx.y;
    const int dtile = blockIdx.x * 128;
    const uint32_t sb = smem_u32(sm);

    const __nv_bfloat16* Ah = g_ath + (size_t)b * 64 * N_;
    const __nv_bfloat16* Al = g_atl + (size_t)b * 64 * N_;
    const float* Bsrc = inputs + (size_t)b * N_ * D_ + dtile;

    const int arow = tid >> 2, ach = tid & 3;
    const int brow = tid >> 3, bdc = (tid & 7) * 16;

    float acc[2][4][4];
    #pragma unroll
    for (int a = 0; a < 2; a++)
        #pragma unroll
        for (int c = 0; c < 4; c++)
            #pragma unroll
            for (int e = 0; e < 4; e++) acc[a][c][e] = 0.0f;

    const uint32_t a_l = sb + (uint32_t)((wm * 32 + (lane & 15)) * 80 + (lane >> 4) * 16);
    const uint32_t b_l = sb + 10240u +
        (uint32_t)((((lane >> 3) & 1) * 8 + (lane & 7)) * 272 +
                   (wn * 32 + (lane >> 4) * 8) * 2);

    auto ISSUE_A = [&](int stage, int slab) {
        const uint32_t base = sb + (uint32_t)stage * USTAGE;
        uint32_t d0 = base + (uint32_t)arow * 80u + (uint32_t)ach * 16u;
        size_t s0 = (size_t)arow * N_ + slab * 32 + ach * 8;
        cp16(d0,         Ah + s0);
        cp16(d0 + 5120u, Al + s0);
        CP_COMMIT();
    };

    float4 breg[2][4];
    auto LDGB = [&](int slab, int buf) {
        const float* p = Bsrc + (size_t)(slab * 32 + brow) * D_ + bdc;
        #pragma unroll
        for (int q = 0; q < 4; q++) breg[buf][q] = *(const float4*)(p + q * 4);
    };
    auto STSB = [&](int stage, int buf) {
        const uint32_t base = sb + (uint32_t)stage * USTAGE + 10240u +
                              (uint32_t)brow * 272u + (uint32_t)bdc * 2u;
        #pragma unroll
        for (int q = 0; q < 4; q++) {
            uint2 h, l;
            split4(breg[buf][q], h, l);
            *(uint2*)(sm + (base - sb) + q * 8)         = h;
            *(uint2*)(sm + (base - sb) + 8704u + q * 8) = l;
        }
    };

    auto COMP = [&](int stage) {
        uint32_t ab  = a_l + (uint32_t)stage * USTAGE;
        uint32_t bb_ = b_l + (uint32_t)stage * USTAGE;
        #pragma unroll
        for (int ks = 0; ks < 2; ks++) {
            uint32_t ak = ab + ks * 32;
            uint32_t bk = bb_ + ks * 16 * 272;
            uint32_t af[2][4], bh[2][4], bl[2][4];
            #pragma unroll
            for (int mf = 0; mf < 2; mf++) ldsm_x4(af[mf], ak + mf * 1280);
            #pragma unroll
            for (int p = 0; p < 2; p++) ldsm_x4_t(bh[p], bk + p * 32);
            #pragma unroll
            for (int mf = 0; mf < 2; mf++)
                #pragma unroll
                for (int nf = 0; nf < 4; nf++)
                    mma_bf16(acc[mf][nf], af[mf], &bh[nf >> 1][(nf & 1) * 2]);
            #pragma unroll
            for (int p = 0; p < 2; p++) ldsm_x4_t(bl[p], bk + 8704u + p * 32);
            #pragma unroll
            for (int mf = 0; mf < 2; mf++)
                #pragma unroll
                for (int nf = 0; nf < 4; nf++)
                    mma_bf16(acc[mf][nf], af[mf], &bl[nf >> 1][(nf & 1) * 2]);
            #pragma unroll
            for (int mf = 0; mf < 2; mf++) ldsm_x4(af[mf], ak + 5120u + mf * 1280);
            #pragma unroll
            for (int mf = 0; mf < 2; mf++)
                #pragma unroll
                for (int nf = 0; nf < 4; nf++)
                    mma_bf16(acc[mf][nf], af[mf], &bh[nf >> 1][(nf & 1) * 2]);
        }
    };

    LDGB(0, 0);
    ISSUE_A(0, 0);
    ISSUE_A(1, 1);
    for (int i = 0; i < 32; i++) {
        const int s = i & 1;
        if (i < 31) LDGB(i + 1, s ^ 1);
        if (i < 31) { CP_WAIT1(); } else { CP_WAIT0(); }
        __syncthreads();
        STSB(s, s);
        __syncthreads();
        COMP(s);
        __syncthreads();
        if (i < 30) ISSUE_A(s, i + 2);
    }

    const float invd = 1.0f / (float)D_;
    #pragma unroll
    for (int mf = 0; mf < 2; mf++) {
        int i0 = wm * 32 + mf * 16 + (lane >> 2);
        #pragma unroll
        for (int nf = 0; nf < 4; nf++) {
            int col = dtile + wn * 32 + nf * 8 + (lane & 3) * 2;
            if (i0 < S_) {
                float2 v;
                v.x = acc[mf][nf][0] * invd;
                v.y = acc[mf][nf][1] * invd;
                *(float2*)&out[((size_t)b * S_ + i0) * D_ + col] = v;
            }
            if (i0 + 8 < S_) {
                float2 v;
                v.x = acc[mf][nf][2] * invd;
                v.y = acc[mf][nf][3] * invd;
                *(float2*)&out[((size_t)b * S_ + i0 + 8) * D_ + col] = v;
            }
        }
    }
}

// ---------------- launch ---------------------------------------------------------
extern "C" void kernel_launch(void* const* d_in, const int* in_sizes, int n_in,
                              void* d_out, int out_size) {
    const float* inputs_pe = (const float*)d_in[0];
    const float* inputs    = (const float*)d_in[1];
    const float* slots     = (const float*)d_in[2];
    const float* W1 = (const float*)d_in[3];
    const float* b1 = (const float*)d_in[4];
    const float* W2 = (const float*)d_in[5];
    const float* b2 = (const float*)d_in[6];
    const float* W3 = (const float*)d_in[7];
    const float* b3 = (const float*)d_in[8];
    float* out = (float*)d_out;

    __nv_bfloat16 *p0h, *p0l, *p1h, *p1l, *wh, *wl;
    float *attn_fb;
    cudaGetSymbolAddress((void**)&p0h, g_p0h);
    cudaGetSymbolAddress((void**)&p0l, g_p0l);
    cudaGetSymbolAddress((void**)&p1h, g_p1h);
    cudaGetSymbolAddress((void**)&p1l, g_p1l);
    cudaGetSymbolAddress((void**)&wh,  g_wh);
    cudaGetSymbolAddress((void**)&wl,  g_wl);
    cudaGetSymbolAddress((void**)&attn_fb, g_attn_fb);

    const size_t updates_elems = (size_t)B_ * S_ * D_;
    const size_t attn_elems    = (size_t)B_ * S_ * N_;
    float* attn_ptr = out + updates_elems;
    if ((size_t)out_size < updates_elems + attn_elems) attn_ptr = attn_fb;

    cudaFuncSetAttribute(sc_pipe_gemm<1>, cudaFuncAttributeMaxDynamicSharedMemorySize, GSMEM);
    cudaFuncSetAttribute(sc_dots_mma,     cudaFuncAttributeMaxDynamicSharedMemorySize, DSMEM);
    cudaFuncSetAttribute(sc_updates_mma,  cudaFuncAttributeMaxDynamicSharedMemorySize, USMEM);

    sc_zero_kernel<<<(B_ * 64 + 255) / 256, 256>>>();
    {
        int n4 = (M_ * D_) / 4;
        sc_split_kernel<<<(n4 + 255) / 256, 256>>>(inputs_pe, p0h, p0l, n4);
        int w4 = (D_ * D_) / 4;
        sc_split_kernel<<<(w4 + 255) / 256, 256>>>(W1, wh + 0 * D_ * D_, wl + 0 * D_ * D_, w4);
        sc_split_kernel<<<(w4 + 255) / 256, 256>>>(W2, wh + 1 * D_ * D_, wl + 1 * D_ * D_, w4);
    }
    {
        dim3 gv3(64, 8);
        sc_v3_kernel<<<gv3, 256>>>(slots, W3, b3);
    }

    dim3 gg(D_ / 128, M_ / 128);
    sc_pipe_gemm<1><<<gg, 256, GSMEM>>>(p0h, p0l, wh + 0 * D_ * D_, wl + 0 * D_ * D_, b1,
                                        p1h, p1l);
    sc_pipe_gemm<1><<<gg, 256, GSMEM>>>(p1h, p1l, wh + 1 * D_ * D_, wl + 1 * D_ * D_, b2,
                                        p0h, p0l);

    sc_dots_mma<<<M_ / 128, 256, DSMEM>>>(p0h, p0l);

    dim3 gsm(N_ / 128, B_);
    sc_softmax_kernel<<<gsm, 128>>>(attn_ptr);

    dim3 gup(D_ / 128, B_);
    sc_updates_mma<<<gup, 256, USMEM>>>(inputs, out);
}

// round 14
// speedup vs baseline: 1.2062x; 1.0111x over previous
#include <cuda_runtime.h>
#include <cuda_bf16.h>
#include <math.h>
#include <stdint.h>

#define B_ 128
#define N_ 1024
#define D_ 512
#define S_ 50
#define M_ (B_ * N_)   // 131072
#define SPAD 64

// ---------------- scratch ----------------------------------------------------
__device__ __nv_bfloat16 g_p0h[(size_t)M_ * D_];
__device__ __nv_bfloat16 g_p0l[(size_t)M_ * D_];
__device__ __nv_bfloat16 g_p1h[(size_t)M_ * D_];
__device__ __nv_bfloat16 g_p1l[(size_t)M_ * D_];
__device__ __nv_bfloat16 g_wh[2][D_ * D_];
__device__ __nv_bfloat16 g_wl[2][D_ * D_];
__device__ __nv_bfloat16 g_v3h[64 * D_];
__device__ __nv_bfloat16 g_v3l[64 * D_];
__device__ float g_db[64];
__device__ float g_dots[(size_t)B_ * N_ * SPAD];
__device__ float g_rowsum[B_ * 64];
__device__ float g_attn_fb[(size_t)B_ * S_ * N_];
__device__ __nv_bfloat16 g_ath[(size_t)B_ * 64 * N_];
__device__ __nv_bfloat16 g_atl[(size_t)B_ * 64 * N_];

// ---------------- helpers ----------------------------------------------------
__device__ __forceinline__ uint32_t smem_u32(const void* p) {
    uint32_t a;
    asm("{ .reg .u64 t; cvta.to.shared.u64 t, %1; cvt.u32.u64 %0, t; }" : "=r"(a) : "l"(p));
    return a;
}
__device__ __forceinline__ void ldsm_x4(uint32_t* r, uint32_t addr) {
    asm volatile("ldmatrix.sync.aligned.m8n8.x4.shared.b16 {%0,%1,%2,%3}, [%4];"
                 : "=r"(r[0]), "=r"(r[1]), "=r"(r[2]), "=r"(r[3]) : "r"(addr));
}
__device__ __forceinline__ void ldsm_x4_t(uint32_t* r, uint32_t addr) {
    asm volatile("ldmatrix.sync.aligned.m8n8.x4.trans.shared.b16 {%0,%1,%2,%3}, [%4];"
                 : "=r"(r[0]), "=r"(r[1]), "=r"(r[2]), "=r"(r[3]) : "r"(addr));
}
__device__ __forceinline__ void mma_bf16(float* d, const uint32_t* a, const uint32_t* b) {
    asm volatile("mma.sync.aligned.m16n8k16.row.col.f32.bf16.bf16.f32 "
                 "{%0,%1,%2,%3},{%4,%5,%6,%7},{%8,%9},{%0,%1,%2,%3};"
                 : "+f"(d[0]), "+f"(d[1]), "+f"(d[2]), "+f"(d[3])
                 : "r"(a[0]), "r"(a[1]), "r"(a[2]), "r"(a[3]), "r"(b[0]), "r"(b[1]));
}
__device__ __forceinline__ void cp16(uint32_t dst, const void* src) {
    asm volatile("cp.async.cg.shared.global [%0], [%1], 16;" :: "r"(dst), "l"(src));
}
#define CP_COMMIT() asm volatile("cp.async.commit_group;" ::: "memory")
#define CP_WAIT1()  asm volatile("cp.async.wait_group 1;" ::: "memory")
#define CP_WAIT0()  asm volatile("cp.async.wait_group 0;" ::: "memory")

__device__ __forceinline__ uint32_t pack_bf16(__nv_bfloat16 a, __nv_bfloat16 b) {
    __nv_bfloat162 t = __halves2bfloat162(a, b);
    return *reinterpret_cast<uint32_t*>(&t);
}
__device__ __forceinline__ void split4(float4 v, uint2& hi, uint2& lo) {
    __nv_bfloat16 hx = __float2bfloat16(v.x), hy = __float2bfloat16(v.y);
    __nv_bfloat16 hz = __float2bfloat16(v.z), hw = __float2bfloat16(v.w);
    __nv_bfloat16 lx = __float2bfloat16(v.x - __bfloat162float(hx));
    __nv_bfloat16 ly = __float2bfloat16(v.y - __bfloat162float(hy));
    __nv_bfloat16 lz = __float2bfloat16(v.z - __bfloat162float(hz));
    __nv_bfloat16 lw = __float2bfloat16(v.w - __bfloat162float(hw));
    hi = make_uint2(pack_bf16(hx, hy), pack_bf16(hz, hw));
    lo = make_uint2(pack_bf16(lx, ly), pack_bf16(lz, lw));
}

// ---------------- misc small kernels ------------------------------------------
__global__ void sc_zero_kernel() {
    int i = blockIdx.x * blockDim.x + threadIdx.x;
    if (i < B_ * 64) g_rowsum[i] = 0.0f;
}
__global__ void sc_split_kernel(const float* __restrict__ src, __nv_bfloat16* __restrict__ hi,
                                __nv_bfloat16* __restrict__ lo, int n4) {
    int i = blockIdx.x * blockDim.x + threadIdx.x;
    if (i < n4) {
        float4 v = ((const float4*)src)[i];
        uint2 h, l;
        split4(v, h, l);
        ((uint2*)hi)[i] = h;
        ((uint2*)lo)[i] = l;
    }
}

// V3[i,:] = slots[i,:] @ W3 (bf16 hi/lo); db[i] = b3 . slots[i]
__global__ __launch_bounds__(256)
void sc_v3_kernel(const float* __restrict__ slots, const float* __restrict__ W3,
                  const float* __restrict__ b3) {
    int i = blockIdx.x;
    int ebase = blockIdx.y * 64;
    __shared__ float srow[D_];
    for (int d = threadIdx.x; d < D_; d += 256)
        srow[d] = (i < S_) ? slots[i * D_ + d] : 0.0f;
    __syncthreads();
    int el = threadIdx.x >> 2, ks = threadIdx.x & 3;
    int e = ebase + el;
    float s = 0.0f;
    #pragma unroll 8
    for (int d = ks * 128; d < ks * 128 + 128; d++)
        s = fmaf(srow[d], W3[(size_t)d * D_ + e], s);
    s += __shfl_xor_sync(0xffffffffu, s, 1);
    s += __shfl_xor_sync(0xffffffffu, s, 2);
    if (ks == 0) {
        __nv_bfloat16 h = __float2bfloat16(s);
        __nv_bfloat16 l = __float2bfloat16(s - __bfloat162float(h));
        g_v3h[i * D_ + e] = h;
        g_v3l[i * D_ + e] = l;
    }
    if (blockIdx.y == 0) {
        __shared__ float red[256];
        float p = 0.0f;
        for (int d = threadIdx.x; d < D_; d += 256) p = fmaf(b3[d], srow[d], p);
        red[threadIdx.x] = p;
        __syncthreads();
        for (int w = 128; w > 0; w >>= 1) {
            if (threadIdx.x < w) red[threadIdx.x] += red[threadIdx.x + w];
            __syncthreads();
        }
        if (threadIdx.x == 0) g_db[i] = red[0];
    }
}

// ---------------- pipelined bf16-split GEMM (round-10 geometry) ----------------
#define GSTAGE 40960
#define GSMEM  (2 * GSTAGE)
template<int RELU>
__global__ __launch_bounds__(256, 2)
void sc_pipe_gemm(const __nv_bfloat16* __restrict__ Ahi, const __nv_bfloat16* __restrict__ Alo,
                  const __nv_bfloat16* __restrict__ Bhi, const __nv_bfloat16* __restrict__ Blo,
                  const float* __restrict__ bias,
                  __nv_bfloat16* __restrict__ Chi, __nv_bfloat16* __restrict__ Clo) {
    extern __shared__ char sm[];
    const int tid = threadIdx.x;
    const int wid = tid >> 5, lane = tid & 31;
    const int wm = wid & 1, wn = wid >> 1;
    const int mbase = blockIdx.y * 128;
    const int nbase = blockIdx.x * 128;
    const uint32_t sb = smem_u32(sm);

    const __nv_bfloat16* Ah = Ahi + (size_t)mbase * D_;
    const __nv_bfloat16* Al = Alo + (size_t)mbase * D_;
    const __nv_bfloat16* Bh = Bhi + (size_t)nbase * D_;
    const __nv_bfloat16* Bl = Blo + (size_t)nbase * D_;

    const int idx0 = tid * 2;
    const int prow0 = idx0 >> 2,        pch0 = (idx0 & 3);
    const int prow1 = (idx0 + 1) >> 2,  pch1 = ((idx0 + 1) & 3);

    float brg[4][2];
    #pragma unroll
    for (int nf = 0; nf < 4; nf++) {
        int col = nbase + wn * 32 + nf * 8 + (lane & 3) * 2;
        brg[nf][0] = bias[col];
        brg[nf][1] = bias[col + 1];
    }

    float acc[4][4][4];
    #pragma unroll
    for (int a = 0; a < 4; a++)
        #pragma unroll
        for (int b = 0; b < 4; b++)
            #pragma unroll
            for (int c = 0; c < 4; c++) acc[a][b][c] = 0.0f;

    const uint32_t a_l = sb + (uint32_t)((wm * 64 + (lane & 15)) * 80 + (lane >> 4) * 16);
    const uint32_t b_l = sb + 20480u +
        (uint32_t)((wn * 32 + ((lane >> 4) & 1) * 8 + (lane & 7)) * 80 + ((lane >> 3) & 1) * 16);

    auto ISSUE = [&](int stage, int slab) {
        const int k0 = slab * 32;
        const uint32_t base = sb + (uint32_t)stage * GSTAGE;
        uint32_t d0 = base + (uint32_t)prow0 * 80u + (uint32_t)pch0 * 16u;
        uint32_t d1 = base + (uint32_t)prow1 * 80u + (uint32_t)pch1 * 16u;
        size_t s0 = (size_t)prow0 * D_ + k0 + pch0 * 8;
        size_t s1 = (size_t)prow1 * D_ + k0 + pch1 * 8;
        cp16(d0,          Ah + s0);  cp16(d1,          Ah + s1);
        cp16(d0 + 10240u, Al + s0);  cp16(d1 + 10240u, Al + s1);
        cp16(d0 + 20480u, Bh + s0);  cp16(d1 + 20480u, Bh + s1);
        cp16(d0 + 30720u, Bl + s0);  cp16(d1 + 30720u, Bl + s1);
        CP_COMMIT();
    };

    auto COMP = [&](int stage) {
        uint32_t ab  = a_l + (uint32_t)stage * GSTAGE;
        uint32_t bb_ = b_l + (uint32_t)stage * GSTAGE;
        #pragma unroll
        for (int ks = 0; ks < 2; ks++) {
            uint32_t ak = ab + ks * 32;
            uint32_t bk = bb_ + ks * 32;
            uint32_t af[4][4], b0[2][4], b1[2][4];
            #pragma unroll
            for (int mf = 0; mf < 4; mf++) ldsm_x4(af[mf], ak + mf * 1280);
            #pragma unroll
            for (int p = 0; p < 2; p++) ldsm_x4(b0[p], bk + p * 1280);
            #pragma unroll
            for (int mf = 0; mf < 4; mf++)
                #pragma unroll
                for (int nf = 0; nf < 4; nf++)
                    mma_bf16(acc[mf][nf], af[mf], &b0[nf >> 1][(nf & 1) * 2]);
            #pragma unroll
            for (int p = 0; p < 2; p++) ldsm_x4(b1[p], bk + 10240 + p * 1280);
            #pragma unroll
            for (int mf = 0; mf < 4; mf++)
                #pragma unroll
                for (int nf = 0; nf < 4; nf++)
                    mma_bf16(acc[mf][nf], af[mf], &b1[nf >> 1][(nf & 1) * 2]);
            #pragma unroll
            for (int mf = 0; mf < 4; mf++) ldsm_x4(af[mf], ak + 10240 + mf * 1280);
            #pragma unroll
            for (int mf = 0; mf < 4; mf++)
                #pragma unroll
                for (int nf = 0; nf < 4; nf++)
                    mma_bf16(acc[mf][nf], af[mf], &b0[nf >> 1][(nf & 1) * 2]);
        }
    };

    ISSUE(0, 0);
    ISSUE(1, 1);
    for (int i = 0; i < 16; i++) {
        if (i < 15) { CP_WAIT1(); } else { CP_WAIT0(); }
        __syncthreads();
        COMP(i & 1);
        __syncthreads();
        if (i < 14) ISSUE(i & 1, i + 2);
    }

    #pragma unroll
    for (int mf = 0; mf < 4; mf++) {
        int row0 = mbase + wm * 64 + mf * 16 + (lane >> 2);
        #pragma unroll
        for (int nf = 0; nf < 4; nf++) {
            int col = nbase + wn * 32 + nf * 8 + (lane & 3) * 2;
            float2 v0, v1;
            v0.x = acc[mf][nf][0] + brg[nf][0];
            v0.y = acc[mf][nf][1] + brg[nf][1];
            v1.x = acc[mf][nf][2] + brg[nf][0];
            v1.y = acc[mf][nf][3] + brg[nf][1];
            if (RELU) {
                v0.x = fmaxf(v0.x, 0.f); v0.y = fmaxf(v0.y, 0.f);
                v1.x = fmaxf(v1.x, 0.f); v1.y = fmaxf(v1.y, 0.f);
            }
            __nv_bfloat16 h0 = __float2bfloat16(v0.x), h1 = __float2bfloat16(v0.y);
            __nv_bfloat16 h2 = __float2bfloat16(v1.x), h3 = __float2bfloat16(v1.y);
            __nv_bfloat16 l0 = __float2bfloat16(v0.x - __bfloat162float(h0));
            __nv_bfloat16 l1 = __float2bfloat16(v0.y - __bfloat162float(h1));
            __nv_bfloat16 l2 = __float2bfloat16(v1.x - __bfloat162float(h2));
            __nv_bfloat16 l3 = __float2bfloat16(v1.y - __bfloat162float(h3));
            *(uint32_t*)&Chi[(size_t)row0 * D_ + col]       = pack_bf16(h0, h1);
            *(uint32_t*)&Chi[(size_t)(row0 + 8) * D_ + col] = pack_bf16(h2, h3);
            *(uint32_t*)&Clo[(size_t)row0 * D_ + col]       = pack_bf16(l0, l1);
            *(uint32_t*)&Clo[(size_t)(row0 + 8) * D_ + col] = pack_bf16(l2, l3);
        }
    }
}

// ---------------- dots via mma + fused rowsum ----------------------------------
#define DSTAGE 30720
#define DSMEM  (2 * DSTAGE)
__global__ __launch_bounds__(256, 2)
void sc_dots_mma(const __nv_bfloat16* __restrict__ Ahi, const __nv_bfloat16* __restrict__ Alo) {
    extern __shared__ char sm[];
    const int tid = threadIdx.x;
    const int wid = tid >> 5, lane = tid & 31;
    const int mbase = blockIdx.x * 128;
    const uint32_t sb = smem_u32(sm);
    __shared__ float sdb[64];
    __shared__ float rsum[8][64];
    if (tid < 64) sdb[tid] = g_db[tid];

    const __nv_bfloat16* Ah = Ahi + (size_t)mbase * D_;
    const __nv_bfloat16* Al = Alo + (size_t)mbase * D_;

    const int prow = tid >> 1, pch0 = (tid & 1) * 2, pch1 = pch0 + 1;
    const int brow = tid >> 2, bch = tid & 3;

    float acc[8][4];
    #pragma unroll
    for (int u = 0; u < 8; u++)
        #pragma unroll
        for (int v = 0; v < 4; v++) acc[u][v] = 0.0f;

    const uint32_t a_l = sb + (uint32_t)((wid * 16 + (lane & 15)) * 80 + (lane >> 4) * 16);
    const uint32_t b_l = sb + 20480u +
        (uint32_t)((((lane >> 4) & 1) * 8 + (lane & 7)) * 80 + ((lane >> 3) & 1) * 16);

    auto ISSUE = [&](int stage, int slab) {
        const int k0 = slab * 32;
        const uint32_t base = sb + (uint32_t)stage * DSTAGE;
        uint32_t d0 = base + (uint32_t)prow * 80u + (uint32_t)pch0 * 16u;
        size_t s0 = (size_t)prow * D_ + k0 + pch0 * 8;
        size_t s1 = (size_t)prow * D_ + k0 + pch1 * 8;
        cp16(d0,          Ah + s0);  cp16(d0 + 16u,          Ah + s1);
        cp16(d0 + 10240u, Al + s0);  cp16(d0 + 10240u + 16u, Al + s1);
        uint32_t db_ = base + 20480u + (uint32_t)brow * 80u + (uint32_t)bch * 16u;
        size_t sB = (size_t)brow * D_ + k0 + bch * 8;
        cp16(db_,         g_v3h + sB);
        cp16(db_ + 5120u, g_v3l + sB);
        CP_COMMIT();
    };

    auto COMP = [&](int stage) {
        uint32_t ab  = a_l + (uint32_t)stage * DSTAGE;
        uint32_t bb_ = b_l + (uint32_t)stage * DSTAGE;
        #pragma unroll
        for (int ks = 0; ks < 2; ks++) {
            uint32_t ak = ab + ks * 32;
            uint32_t bk = bb_ + ks * 32;
            uint32_t af[4], bh[4][4], bl[4][4];
            ldsm_x4(af, ak);
            #pragma unroll
            for (int p = 0; p < 4; p++) ldsm_x4(bh[p], bk + p * 1280);
            #pragma unroll
            for (int nf = 0; nf < 8; nf++)
                mma_bf16(acc[nf], af, &bh[nf >> 1][(nf & 1) * 2]);
            #pragma unroll
            for (int p = 0; p < 4; p++) ldsm_x4(bl[p], bk + 5120 + p * 1280);
            #pragma unroll
            for (int nf = 0; nf < 8; nf++)
                mma_bf16(acc[nf], af, &bl[nf >> 1][(nf & 1) * 2]);
            ldsm_x4(af, ak + 10240);
            #pragma unroll
            for (int nf = 0; nf < 8; nf++)
                mma_bf16(acc[nf], af, &bh[nf >> 1][(nf & 1) * 2]);
        }
    };

    ISSUE(0, 0);
    ISSUE(1, 1);
    for (int i = 0; i < 16; i++) {
        if (i < 15) { CP_WAIT1(); } else { CP_WAIT0(); }
        __syncthreads();
        COMP(i & 1);
        __syncthreads();
        if (i < 14) ISSUE(i & 1, i + 2);
    }

    const float scale = 0.04419417382415922f;
    const int b  = mbase / N_;
    const int jb = mbase % N_;
    const int r0 = jb + wid * 16 + (lane >> 2);
    #pragma unroll
    for (int nf = 0; nf < 8; nf++) {
        int col = nf * 8 + (lane & 3) * 2;
        float dbx = sdb[col], dby = sdb[col + 1];
        float2 v0, v1;
        v0.x = (acc[nf][0] + dbx) * scale;
        v0.y = (acc[nf][1] + dby) * scale;
        v1.x = (acc[nf][2] + dbx) * scale;
        v1.y = (acc[nf][3] + dby) * scale;
        *(float2*)&g_dots[((size_t)b * N_ + r0) * SPAD + col]     = v0;
        *(float2*)&g_dots[((size_t)b * N_ + r0 + 8) * SPAD + col] = v1;
        float s0 = v0.x + v1.x;
        float s1 = v0.y + v1.y;
        #pragma unroll
        for (int off = 4; off < 32; off <<= 1) {
            s0 += __shfl_down_sync(0xffffffffu, s0, off);
            s1 += __shfl_down_sync(0xffffffffu, s1, off);
        }
        if (lane < 4) {
            rsum[wid][nf * 8 + lane * 2]     = s0;
            rsum[wid][nf * 8 + lane * 2 + 1] = s1;
        }
    }
    __syncthreads();
    if (tid < 64) {
        float t = 0.0f;
        #pragma unroll
        for (int w = 0; w < 8; w++) t += rsum[w][tid];
        atomicAdd(&g_rowsum[b * 64 + tid], t);
    }
}

// ---------------- softmax -------------------------------------------------------
__global__ __launch_bounds__(128)
void sc_softmax_kernel(float* __restrict__ attn_out) {
    int b = blockIdx.y;
    int j = blockIdx.x * 128 + threadIdx.x;
    __shared__ float inv_rs[S_];
    __shared__ float rs_raw[S_];
    if (threadIdx.x < S_) {
        float r = g_rowsum[b * 64 + threadIdx.x];
        rs_raw[threadIdx.x] = r;
        inv_rs[threadIdx.x] = 1.0f / r;
    }
    __syncthreads();
    float tot = 0.0f;
    #pragma unroll
    for (int i = 0; i < S_; i++) tot += rs_raw[i];
    const float* src = &g_dots[((size_t)b * N_ + j) * SPAD];
    float dn[S_];
    float m = -INFINITY;
    #pragma unroll
    for (int i = 0; i < S_; i++) {
        float v = src[i] * inv_rs[i] * tot;
        dn[i] = v;
        m = fmaxf(m, v);
    }
    float s = 0.f;
    #pragma unroll
    for (int i = 0; i < S_; i++) s += expf(dn[i] - m);
    float inv_s = 1.0f / s;
    #pragma unroll
    for (int i = 0; i < S_; i++) {
        float sm  = expf(dn[i] - m) * inv_s;
        float sig = 1.0f / (1.0f + expf(-dn[i]));
        float a = sm * sig;
        attn_out[((size_t)b * S_ + i) * N_ + j] = a;
        __nv_bfloat16 h = __float2bfloat16(a);
        __nv_bfloat16 l = __float2bfloat16(a - __bfloat162float(h));
        g_ath[((size_t)b * 64 + i) * N_ + j] = h;
        g_atl[((size_t)b * 64 + i) * N_ + j] = l;
    }
}

// ---------------- updates via mma (single-sync pipeline) ------------------------
#define USTAGE 27648
#define USMEM  (2 * USTAGE)
__global__ __launch_bounds__(256, 2)
void sc_updates_mma(const float* __restrict__ inputs, float* __restrict__ out) {
    extern __shared__ char sm[];
    const int tid = threadIdx.x;
    const int wid = tid >> 5, lane = tid & 31;
    const int wm = wid & 1, wn = wid >> 1;
    const int b = blockIdx.y;
    const int dtile = blockIdx.x * 128;
    const uint32_t sb = smem_u32(sm);

    const __nv_bfloat16* Ah = g_ath + (size_t)b * 64 * N_;
    const __nv_bfloat16* Al = g_atl + (size_t)b * 64 * N_;
    const float* Bsrc = inputs + (size_t)b * N_ * D_ + dtile;

    const int arow = tid >> 2, ach = tid & 3;
    const int brow = tid >> 3, bdc = (tid & 7) * 16;

    float acc[2][4][4];
    #pragma unroll
    for (int a = 0; a < 2; a++)
        #pragma unroll
        for (int c = 0; c < 4; c++)
            #pragma unroll
            for (int e = 0; e < 4; e++) acc[a][c][e] = 0.0f;

    const uint32_t a_l = sb + (uint32_t)((wm * 32 + (lane & 15)) * 80 + (lane >> 4) * 16);
    const uint32_t b_l = sb + 10240u +
        (uint32_t)((((lane >> 3) & 1) * 8 + (lane & 7)) * 272 +
                   (wn * 32 + (lane >> 4) * 8) * 2);

    auto ISSUE_A = [&](int stage, int slab) {
        const uint32_t base = sb + (uint32_t)stage * USTAGE;
        uint32_t d0 = base + (uint32_t)arow * 80u + (uint32_t)ach * 16u;
        size_t s0 = (size_t)arow * N_ + slab * 32 + ach * 8;
        cp16(d0,         Ah + s0);
        cp16(d0 + 5120u, Al + s0);
        CP_COMMIT();
    };

    float4 breg[2][4];
    auto LDGB = [&](int slab, int buf) {
        const float* p = Bsrc + (size_t)(slab * 32 + brow) * D_ + bdc;
        #pragma unroll
        for (int q = 0; q < 4; q++) breg[buf][q] = *(const float4*)(p + q * 4);
    };
    auto STSB = [&](int stage, int buf) {
        const uint32_t off = (uint32_t)stage * USTAGE + 10240u +
                             (uint32_t)brow * 272u + (uint32_t)bdc * 2u;
        #pragma unroll
        for (int q = 0; q < 4; q++) {
            uint2 h, l;
            split4(breg[buf][q], h, l);
            *(uint2*)(sm + off + q * 8)         = h;
            *(uint2*)(sm + off + 8704u + q * 8) = l;
        }
    };

    auto COMP = [&](int stage) {
        uint32_t ab  = a_l + (uint32_t)stage * USTAGE;
        uint32_t bb_ = b_l + (uint32_t)stage * USTAGE;
        #pragma unroll
        for (int ks = 0; ks < 2; ks++) {
            uint32_t ak = ab + ks * 32;
            uint32_t bk = bb_ + ks * 16 * 272;
            uint32_t af[2][4], bh[2][4], bl[2][4];
            #pragma unroll
            for (int mf = 0; mf < 2; mf++) ldsm_x4(af[mf], ak + mf * 1280);
            #pragma unroll
            for (int p = 0; p < 2; p++) ldsm_x4_t(bh[p], bk + p * 32);
            #pragma unroll
            for (int mf = 0; mf < 2; mf++)
                #pragma unroll
                for (int nf = 0; nf < 4; nf++)
                    mma_bf16(acc[mf][nf], af[mf], &bh[nf >> 1][(nf & 1) * 2]);
            #pragma unroll
            for (int p = 0; p < 2; p++) ldsm_x4_t(bl[p], bk + 8704u + p * 32);
            #pragma unroll
            for (int mf = 0; mf < 2; mf++)
                #pragma unroll
                for (int nf = 0; nf < 4; nf++)
                    mma_bf16(acc[mf][nf], af[mf], &bl[nf >> 1][(nf & 1) * 2]);
            #pragma unroll
            for (int mf = 0; mf < 2; mf++) ldsm_x4(af[mf], ak + 5120u + mf * 1280);
            #pragma unroll
            for (int mf = 0; mf < 2; mf++)
                #pragma unroll
                for (int nf = 0; nf < 4; nf++)
                    mma_bf16(acc[mf][nf], af[mf], &bh[nf >> 1][(nf & 1) * 2]);
        }
    };

    // prologue: slab0 fully staged into stage0; slab1 B prefetched to regs
    LDGB(0, 0);
    LDGB(1, 1);
    ISSUE_A(0, 0);          // group for slab 0 (stage 0)
    STSB(0, 0);             // B slab 0 -> stage 0

    for (int i = 0; i < 32; i++) {
        const int s = i & 1;
        CP_WAIT0();         // A(stage s, slab i) complete
        __syncthreads();    // STS(B stage s) visible; stage s^1 consumed by all warps
        if (i < 31) {
            ISSUE_A(s ^ 1, i + 1);       // A slab i+1 -> freed stage
            STSB(s ^ 1, (i + 1) & 1);    // B slab i+1 -> freed stage
        }
        if (i < 30) LDGB(i + 2, i & 1);  // prefetch regs (buf held slab i, already staged)
        COMP(s);
    }

    const float invd = 1.0f / (float)D_;
    #pragma unroll
    for (int mf = 0; mf < 2; mf++) {
        int i0 = wm * 32 + mf * 16 + (lane >> 2);
        #pragma unroll
        for (int nf = 0; nf < 4; nf++) {
            int col = dtile + wn * 32 + nf * 8 + (lane & 3) * 2;
            if (i0 < S_) {
                float2 v;
                v.x = acc[mf][nf][0] * invd;
                v.y = acc[mf][nf][1] * invd;
                *(float2*)&out[((size_t)b * S_ + i0) * D_ + col] = v;
            }
            if (i0 + 8 < S_) {
                float2 v;
                v.x = acc[mf][nf][2] * invd;
                v.y = acc[mf][nf][3] * invd;
                *(float2*)&out[((size_t)b * S_ + i0 + 8) * D_ + col] = v;
            }
        }
    }
}

// ---------------- launch ---------------------------------------------------------
extern "C" void kernel_launch(void* const* d_in, const int* in_sizes, int n_in,
                              void* d_out, int out_size) {
    const float* inputs_pe = (const float*)d_in[0];
    const float* inputs    = (const float*)d_in[1];
    const float* slots     = (const float*)d_in[2];
    const float* W1 = (const float*)d_in[3];
    const float* b1 = (const float*)d_in[4];
    const float* W2 = (const float*)d_in[5];
    const float* b2 = (const float*)d_in[6];
    const float* W3 = (const float*)d_in[7];
    const float* b3 = (const float*)d_in[8];
    float* out = (float*)d_out;

    __nv_bfloat16 *p0h, *p0l, *p1h, *p1l, *wh, *wl;
    float *attn_fb;
    cudaGetSymbolAddress((void**)&p0h, g_p0h);
    cudaGetSymbolAddress((void**)&p0l, g_p0l);
    cudaGetSymbolAddress((void**)&p1h, g_p1h);
    cudaGetSymbolAddress((void**)&p1l, g_p1l);
    cudaGetSymbolAddress((void**)&wh,  g_wh);
    cudaGetSymbolAddress((void**)&wl,  g_wl);
    cudaGetSymbolAddress((void**)&attn_fb, g_attn_fb);

    const size_t updates_elems = (size_t)B_ * S_ * D_;
    const size_t attn_elems    = (size_t)B_ * S_ * N_;
    float* attn_ptr = out + updates_elems;
    if ((size_t)out_size < updates_elems + attn_elems) attn_ptr = attn_fb;

    cudaFuncSetAttribute(sc_pipe_gemm<1>, cudaFuncAttributeMaxDynamicSharedMemorySize, GSMEM);
    cudaFuncSetAttribute(sc_dots_mma,     cudaFuncAttributeMaxDynamicSharedMemorySize, DSMEM);
    cudaFuncSetAttribute(sc_updates_mma,  cudaFuncAttributeMaxDynamicSharedMemorySize, USMEM);

    sc_zero_kernel<<<(B_ * 64 + 255) / 256, 256>>>();
    {
        int n4 = (M_ * D_) / 4;
        sc_split_kernel<<<(n4 + 255) / 256, 256>>>(inputs_pe, p0h, p0l, n4);
        int w4 = (D_ * D_) / 4;
        sc_split_kernel<<<(w4 + 255) / 256, 256>>>(W1, wh + 0 * D_ * D_, wl + 0 * D_ * D_, w4);
        sc_split_kernel<<<(w4 + 255) / 256, 256>>>(W2, wh + 1 * D_ * D_, wl + 1 * D_ * D_, w4);
    }
    {
        dim3 gv3(64, 8);
        sc_v3_kernel<<<gv3, 256>>>(slots, W3, b3);
    }

    dim3 gg(D_ / 128, M_ / 128);
    sc_pipe_gemm<1><<<gg, 256, GSMEM>>>(p0h, p0l, wh + 0 * D_ * D_, wl + 0 * D_ * D_, b1,
                                        p1h, p1l);
    sc_pipe_gemm<1><<<gg, 256, GSMEM>>>(p1h, p1l, wh + 1 * D_ * D_, wl + 1 * D_ * D_, b2,
                                        p0h, p0l);

    sc_dots_mma<<<M_ / 128, 256, DSMEM>>>(p0h, p0l);

    dim3 gsm(N_ / 128, B_);
    sc_softmax_kernel<<<gsm, 128>>>(attn_ptr);

    dim3 gup(D_ / 128, B_);
    sc_updates_mma<<<gup, 256, USMEM>>>(inputs, out);
}

// round 15
// speedup vs baseline: 1.2537x; 1.0394x over previous
#include <cuda_runtime.h>
#include <cuda_bf16.h>
#include <math.h>
#include <stdint.h>

#define B_ 128
#define N_ 1024
#define D_ 512
#define S_ 50
#define M_ (B_ * N_)   // 131072
#define SPAD 64

// ---------------- scratch ----------------------------------------------------
__device__ __nv_bfloat16 g_p0h[(size_t)M_ * D_];
__device__ __nv_bfloat16 g_p0l[(size_t)M_ * D_];
__device__ __nv_bfloat16 g_p1h[(size_t)M_ * D_];
__device__ __nv_bfloat16 g_p1l[(size_t)M_ * D_];
__device__ __nv_bfloat16 g_wh[2][D_ * D_];
__device__ __nv_bfloat16 g_wl[2][D_ * D_];
__device__ __nv_bfloat16 g_v3h[64 * D_];
__device__ __nv_bfloat16 g_v3l[64 * D_];
__device__ float g_db[64];
__device__ float g_dots[(size_t)B_ * N_ * SPAD];
__device__ float g_rowsum[B_ * 64];
__device__ float g_attn_fb[(size_t)B_ * S_ * N_];
__device__ __nv_bfloat16 g_ath[(size_t)B_ * 64 * N_];
__device__ __nv_bfloat16 g_atl[(size_t)B_ * 64 * N_];

// ---------------- helpers ----------------------------------------------------
__device__ __forceinline__ uint32_t smem_u32(const void* p) {
    uint32_t a;
    asm("{ .reg .u64 t; cvta.to.shared.u64 t, %1; cvt.u32.u64 %0, t; }" : "=r"(a) : "l"(p));
    return a;
}
__device__ __forceinline__ void ldsm_x4(uint32_t* r, uint32_t addr) {
    asm volatile("ldmatrix.sync.aligned.m8n8.x4.shared.b16 {%0,%1,%2,%3}, [%4];"
                 : "=r"(r[0]), "=r"(r[1]), "=r"(r[2]), "=r"(r[3]) : "r"(addr));
}
__device__ __forceinline__ void ldsm_x4_t(uint32_t* r, uint32_t addr) {
    asm volatile("ldmatrix.sync.aligned.m8n8.x4.trans.shared.b16 {%0,%1,%2,%3}, [%4];"
                 : "=r"(r[0]), "=r"(r[1]), "=r"(r[2]), "=r"(r[3]) : "r"(addr));
}
__device__ __forceinline__ void mma_bf16(float* d, const uint32_t* a, const uint32_t* b) {
    asm volatile("mma.sync.aligned.m16n8k16.row.col.f32.bf16.bf16.f32 "
                 "{%0,%1,%2,%3},{%4,%5,%6,%7},{%8,%9},{%0,%1,%2,%3};"
                 : "+f"(d[0]), "+f"(d[1]), "+f"(d[2]), "+f"(d[3])
                 : "r"(a[0]), "r"(a[1]), "r"(a[2]), "r"(a[3]), "r"(b[0]), "r"(b[1]));
}
__device__ __forceinline__ void cp16(uint32_t dst, const void* src) {
    asm volatile("cp.async.cg.shared.global [%0], [%1], 16;" :: "r"(dst), "l"(src));
}
#define CP_COMMIT() asm volatile("cp.async.commit_group;" ::: "memory")
#define CP_WAIT0()  asm volatile("cp.async.wait_group 0;" ::: "memory")

__device__ __forceinline__ uint32_t pack_bf16(__nv_bfloat16 a, __nv_bfloat16 b) {
    __nv_bfloat162 t = __halves2bfloat162(a, b);
    return *reinterpret_cast<uint32_t*>(&t);
}
__device__ __forceinline__ void split4(float4 v, uint2& hi, uint2& lo) {
    __nv_bfloat16 hx = __float2bfloat16(v.x), hy = __float2bfloat16(v.y);
    __nv_bfloat16 hz = __float2bfloat16(v.z), hw = __float2bfloat16(v.w);
    __nv_bfloat16 lx = __float2bfloat16(v.x - __bfloat162float(hx));
    __nv_bfloat16 ly = __float2bfloat16(v.y - __bfloat162float(hy));
    __nv_bfloat16 lz = __float2bfloat16(v.z - __bfloat162float(hz));
    __nv_bfloat16 lw = __float2bfloat16(v.w - __bfloat162float(hw));
    hi = make_uint2(pack_bf16(hx, hy), pack_bf16(hz, hw));
    lo = make_uint2(pack_bf16(lx, ly), pack_bf16(lz, lw));
}

// ---------------- misc small kernels ------------------------------------------
__global__ void sc_zero_kernel() {
    int i = blockIdx.x * blockDim.x + threadIdx.x;
    if (i < B_ * 64) g_rowsum[i] = 0.0f;
}
__global__ void sc_split_kernel(const float* __restrict__ src, __nv_bfloat16* __restrict__ hi,
                                __nv_bfloat16* __restrict__ lo, int n4) {
    int i = blockIdx.x * blockDim.x + threadIdx.x;
    if (i < n4) {
        float4 v = ((const float4*)src)[i];
        uint2 h, l;
        split4(v, h, l);
        ((uint2*)hi)[i] = h;
        ((uint2*)lo)[i] = l;
    }
}

// V3[i,:] = slots[i,:] @ W3 (bf16 hi/lo); db[i] = b3 . slots[i]
__global__ __launch_bounds__(256)
void sc_v3_kernel(const float* __restrict__ slots, const float* __restrict__ W3,
                  const float* __restrict__ b3) {
    int i = blockIdx.x;
    int ebase = blockIdx.y * 64;
    __shared__ float srow[D_];
    for (int d = threadIdx.x; d < D_; d += 256)
        srow[d] = (i < S_) ? slots[i * D_ + d] : 0.0f;
    __syncthreads();
    int el = threadIdx.x >> 2, ks = threadIdx.x & 3;
    int e = ebase + el;
    float s = 0.0f;
    #pragma unroll 8
    for (int d = ks * 128; d < ks * 128 + 128; d++)
        s = fmaf(srow[d], W3[(size_t)d * D_ + e], s);
    s += __shfl_xor_sync(0xffffffffu, s, 1);
    s += __shfl_xor_sync(0xffffffffu, s, 2);
    if (ks == 0) {
        __nv_bfloat16 h = __float2bfloat16(s);
        __nv_bfloat16 l = __float2bfloat16(s - __bfloat162float(h));
        g_v3h[i * D_ + e] = h;
        g_v3l[i * D_ + e] = l;
    }
    if (blockIdx.y == 0) {
        __shared__ float red[256];
        float p = 0.0f;
        for (int d = threadIdx.x; d < D_; d += 256) p = fmaf(b3[d], srow[d], p);
        red[threadIdx.x] = p;
        __syncthreads();
        for (int w = 128; w > 0; w >>= 1) {
            if (threadIdx.x < w) red[threadIdx.x] += red[threadIdx.x + w];
            __syncthreads();
        }
        if (threadIdx.x == 0) g_db[i] = red[0];
    }
}

// ---------------- pipelined bf16-split GEMM (single-sync per slab) --------------
#define GSTAGE 40960
#define GSMEM  (2 * GSTAGE)
template<int RELU>
__global__ __launch_bounds__(256, 2)
void sc_pipe_gemm(const __nv_bfloat16* __restrict__ Ahi, const __nv_bfloat16* __restrict__ Alo,
                  const __nv_bfloat16* __restrict__ Bhi, const __nv_bfloat16* __restrict__ Blo,
                  const float* __restrict__ bias,
                  __nv_bfloat16* __restrict__ Chi, __nv_bfloat16* __restrict__ Clo) {
    extern __shared__ char sm[];
    const int tid = threadIdx.x;
    const int wid = tid >> 5, lane = tid & 31;
    const int wm = wid & 1, wn = wid >> 1;
    const int mbase = blockIdx.y * 128;
    const int nbase = blockIdx.x * 128;
    const uint32_t sb = smem_u32(sm);

    const __nv_bfloat16* Ah = Ahi + (size_t)mbase * D_;
    const __nv_bfloat16* Al = Alo + (size_t)mbase * D_;
    const __nv_bfloat16* Bh = Bhi + (size_t)nbase * D_;
    const __nv_bfloat16* Bl = Blo + (size_t)nbase * D_;

    const int idx0 = tid * 2;
    const int prow0 = idx0 >> 2,        pch0 = (idx0 & 3);
    const int prow1 = (idx0 + 1) >> 2,  pch1 = ((idx0 + 1) & 3);

    float brg[4][2];
    #pragma unroll
    for (int nf = 0; nf < 4; nf++) {
        int col = nbase + wn * 32 + nf * 8 + (lane & 3) * 2;
        brg[nf][0] = bias[col];
        brg[nf][1] = bias[col + 1];
    }

    float acc[4][4][4];
    #pragma unroll
    for (int a = 0; a < 4; a++)
        #pragma unroll
        for (int b = 0; b < 4; b++)
            #pragma unroll
            for (int c = 0; c < 4; c++) acc[a][b][c] = 0.0f;

    const uint32_t a_l = sb + (uint32_t)((wm * 64 + (lane & 15)) * 80 + (lane >> 4) * 16);
    const uint32_t b_l = sb + 20480u +
        (uint32_t)((wn * 32 + ((lane >> 4) & 1) * 8 + (lane & 7)) * 80 + ((lane >> 3) & 1) * 16);

    auto ISSUE = [&](int stage, int slab) {
        const int k0 = slab * 32;
        const uint32_t base = sb + (uint32_t)stage * GSTAGE;
        uint32_t d0 = base + (uint32_t)prow0 * 80u + (uint32_t)pch0 * 16u;
        uint32_t d1 = base + (uint32_t)prow1 * 80u + (uint32_t)pch1 * 16u;
        size_t s0 = (size_t)prow0 * D_ + k0 + pch0 * 8;
        size_t s1 = (size_t)prow1 * D_ + k0 + pch1 * 8;
        cp16(d0,          Ah + s0);  cp16(d1,          Ah + s1);
        cp16(d0 + 10240u, Al + s0);  cp16(d1 + 10240u, Al + s1);
        cp16(d0 + 20480u, Bh + s0);  cp16(d1 + 20480u, Bh + s1);
        cp16(d0 + 30720u, Bl + s0);  cp16(d1 + 30720u, Bl + s1);
        CP_COMMIT();
    };

    auto COMP = [&](int stage) {
        uint32_t ab  = a_l + (uint32_t)stage * GSTAGE;
        uint32_t bb_ = b_l + (uint32_t)stage * GSTAGE;
        #pragma unroll
        for (int ks = 0; ks < 2; ks++) {
            uint32_t ak = ab + ks * 32;
            uint32_t bk = bb_ + ks * 32;
            uint32_t af[4][4], b0[2][4], b1[2][4];
            #pragma unroll
            for (int mf = 0; mf < 4; mf++) ldsm_x4(af[mf], ak + mf * 1280);
            #pragma unroll
            for (int p = 0; p < 2; p++) ldsm_x4(b0[p], bk + p * 1280);
            #pragma unroll
            for (int mf = 0; mf < 4; mf++)
                #pragma unroll
                for (int nf = 0; nf < 4; nf++)
                    mma_bf16(acc[mf][nf], af[mf], &b0[nf >> 1][(nf & 1) * 2]);
            #pragma unroll
            for (int p = 0; p < 2; p++) ldsm_x4(b1[p], bk + 10240 + p * 1280);
            #pragma unroll
            for (int mf = 0; mf < 4; mf++)
                #pragma unroll
                for (int nf = 0; nf < 4; nf++)
                    mma_bf16(acc[mf][nf], af[mf], &b1[nf >> 1][(nf & 1) * 2]);
            #pragma unroll
            for (int mf = 0; mf < 4; mf++) ldsm_x4(af[mf], ak + 10240 + mf * 1280);
            #pragma unroll
            for (int mf = 0; mf < 4; mf++)
                #pragma unroll
                for (int nf = 0; nf < 4; nf++)
                    mma_bf16(acc[mf][nf], af[mf], &b0[nf >> 1][(nf & 1) * 2]);
        }
    };

    ISSUE(0, 0);
    for (int i = 0; i < 16; i++) {
        const int s = i & 1;
        CP_WAIT0();         // slab i landed in stage s
        __syncthreads();    // visible to all; stage s^1 consumed by all warps
        if (i < 15) ISSUE(s ^ 1, i + 1);
        COMP(s);
    }

    #pragma unroll
    for (int mf = 0; mf < 4; mf++) {
        int row0 = mbase + wm * 64 + mf * 16 + (lane >> 2);
        #pragma unroll
        for (int nf = 0; nf < 4; nf++) {
            int col = nbase + wn * 32 + nf * 8 + (lane & 3) * 2;
            float2 v0, v1;
            v0.x = acc[mf][nf][0] + brg[nf][0];
            v0.y = acc[mf][nf][1] + brg[nf][1];
            v1.x = acc[mf][nf][2] + brg[nf][0];
            v1.y = acc[mf][nf][3] + brg[nf][1];
            if (RELU) {
                v0.x = fmaxf(v0.x, 0.f); v0.y = fmaxf(v0.y, 0.f);
                v1.x = fmaxf(v1.x, 0.f); v1.y = fmaxf(v1.y, 0.f);
            }
            __nv_bfloat16 h0 = __float2bfloat16(v0.x), h1 = __float2bfloat16(v0.y);
            __nv_bfloat16 h2 = __float2bfloat16(v1.x), h3 = __float2bfloat16(v1.y);
            __nv_bfloat16 l0 = __float2bfloat16(v0.x - __bfloat162float(h0));
            __nv_bfloat16 l1 = __float2bfloat16(v0.y - __bfloat162float(h1));
            __nv_bfloat16 l2 = __float2bfloat16(v1.x - __bfloat162float(h2));
            __nv_bfloat16 l3 = __float2bfloat16(v1.y - __bfloat162float(h3));
            *(uint32_t*)&Chi[(size_t)row0 * D_ + col]       = pack_bf16(h0, h1);
            *(uint32_t*)&Chi[(size_t)(row0 + 8) * D_ + col] = pack_bf16(h2, h3);
            *(uint32_t*)&Clo[(size_t)row0 * D_ + col]       = pack_bf16(l0, l1);
            *(uint32_t*)&Clo[(size_t)(row0 + 8) * D_ + col] = pack_bf16(l2, l3);
        }
    }
}

// ---------------- dots via mma + fused rowsum (single-sync) ---------------------
#define DSTAGE 30720
#define DSMEM  (2 * DSTAGE)
__global__ __launch_bounds__(256, 2)
void sc_dots_mma(const __nv_bfloat16* __restrict__ Ahi, const __nv_bfloat16* __restrict__ Alo) {
    extern __shared__ char sm[];
    const int tid = threadIdx.x;
    const int wid = tid >> 5, lane = tid & 31;
    const int mbase = blockIdx.x * 128;
    const uint32_t sb = smem_u32(sm);
    __shared__ float sdb[64];
    __shared__ float rsum[8][64];
    if (tid < 64) sdb[tid] = g_db[tid];

    const __nv_bfloat16* Ah = Ahi + (size_t)mbase * D_;
    const __nv_bfloat16* Al = Alo + (size_t)mbase * D_;

    const int prow = tid >> 1, pch0 = (tid & 1) * 2, pch1 = pch0 + 1;
    const int brow = tid >> 2, bch = tid & 3;

    float acc[8][4];
    #pragma unroll
    for (int u = 0; u < 8; u++)
        #pragma unroll
        for (int v = 0; v < 4; v++) acc[u][v] = 0.0f;

    const uint32_t a_l = sb + (uint32_t)((wid * 16 + (lane & 15)) * 80 + (lane >> 4) * 16);
    const uint32_t b_l = sb + 20480u +
        (uint32_t)((((lane >> 4) & 1) * 8 + (lane & 7)) * 80 + ((lane >> 3) & 1) * 16);

    auto ISSUE = [&](int stage, int slab) {
        const int k0 = slab * 32;
        const uint32_t base = sb + (uint32_t)stage * DSTAGE;
        uint32_t d0 = base + (uint32_t)prow * 80u + (uint32_t)pch0 * 16u;
        size_t s0 = (size_t)prow * D_ + k0 + pch0 * 8;
        size_t s1 = (size_t)prow * D_ + k0 + pch1 * 8;
        cp16(d0,          Ah + s0);  cp16(d0 + 16u,          Ah + s1);
        cp16(d0 + 10240u, Al + s0);  cp16(d0 + 10240u + 16u, Al + s1);
        uint32_t db_ = base + 20480u + (uint32_t)brow * 80u + (uint32_t)bch * 16u;
        size_t sB = (size_t)brow * D_ + k0 + bch * 8;
        cp16(db_,         g_v3h + sB);
        cp16(db_ + 5120u, g_v3l + sB);
        CP_COMMIT();
    };

    auto COMP = [&](int stage) {
        uint32_t ab  = a_l + (uint32_t)stage * DSTAGE;
        uint32_t bb_ = b_l + (uint32_t)stage * DSTAGE;
        #pragma unroll
        for (int ks = 0; ks < 2; ks++) {
            uint32_t ak = ab + ks * 32;
            uint32_t bk = bb_ + ks * 32;
            uint32_t af[4], bh[4][4], bl[4][4];
            ldsm_x4(af, ak);
            #pragma unroll
            for (int p = 0; p < 4; p++) ldsm_x4(bh[p], bk + p * 1280);
            #pragma unroll
            for (int nf = 0; nf < 8; nf++)
                mma_bf16(acc[nf], af, &bh[nf >> 1][(nf & 1) * 2]);
            #pragma unroll
            for (int p = 0; p < 4; p++) ldsm_x4(bl[p], bk + 5120 + p * 1280);
            #pragma unroll
            for (int nf = 0; nf < 8; nf++)
                mma_bf16(acc[nf], af, &bl[nf >> 1][(nf & 1) * 2]);
            ldsm_x4(af, ak + 10240);
            #pragma unroll
            for (int nf = 0; nf < 8; nf++)
                mma_bf16(acc[nf], af, &bh[nf >> 1][(nf & 1) * 2]);
        }
    };

    ISSUE(0, 0);
    for (int i = 0; i < 16; i++) {
        const int s = i & 1;
        CP_WAIT0();
        __syncthreads();
        if (i < 15) ISSUE(s ^ 1, i + 1);
        COMP(s);
    }

    const float scale = 0.04419417382415922f;
    const int b  = mbase / N_;
    const int jb = mbase % N_;
    const int r0 = jb + wid * 16 + (lane >> 2);
    #pragma unroll
    for (int nf = 0; nf < 8; nf++) {
        int col = nf * 8 + (lane & 3) * 2;
        float dbx = sdb[col], dby = sdb[col + 1];
        float2 v0, v1;
        v0.x = (acc[nf][0] + dbx) * scale;
        v0.y = (acc[nf][1] + dby) * scale;
        v1.x = (acc[nf][2] + dbx) * scale;
        v1.y = (acc[nf][3] + dby) * scale;
        *(float2*)&g_dots[((size_t)b * N_ + r0) * SPAD + col]     = v0;
        *(float2*)&g_dots[((size_t)b * N_ + r0 + 8) * SPAD + col] = v1;
        float s0 = v0.x + v1.x;
        float s1 = v0.y + v1.y;
        #pragma unroll
        for (int off = 4; off < 32; off <<= 1) {
            s0 += __shfl_down_sync(0xffffffffu, s0, off);
            s1 += __shfl_down_sync(0xffffffffu, s1, off);
        }
        if (lane < 4) {
            rsum[wid][nf * 8 + lane * 2]     = s0;
            rsum[wid][nf * 8 + lane * 2 + 1] = s1;
        }
    }
    __syncthreads();
    if (tid < 64) {
        float t = 0.0f;
        #pragma unroll
        for (int w = 0; w < 8; w++) t += rsum[w][tid];
        atomicAdd(&g_rowsum[b * 64 + tid], t);
    }
}

// ---------------- softmax -------------------------------------------------------
__global__ __launch_bounds__(128)
void sc_softmax_kernel(float* __restrict__ attn_out) {
    int b = blockIdx.y;
    int j = blockIdx.x * 128 + threadIdx.x;
    __shared__ float inv_rs[S_];
    __shared__ float rs_raw[S_];
    if (threadIdx.x < S_) {
        float r = g_rowsum[b * 64 + threadIdx.x];
        rs_raw[threadIdx.x] = r;
        inv_rs[threadIdx.x] = 1.0f / r;
    }
    __syncthreads();
    float tot = 0.0f;
    #pragma unroll
    for (int i = 0; i < S_; i++) tot += rs_raw[i];
    const float* src = &g_dots[((size_t)b * N_ + j) * SPAD];
    float dn[S_];
    float m = -INFINITY;
    #pragma unroll
    for (int i = 0; i < S_; i++) {
        float v = src[i] * inv_rs[i] * tot;
        dn[i] = v;
        m = fmaxf(m, v);
    }
    float s = 0.f;
    #pragma unroll
    for (int i = 0; i < S_; i++) s += expf(dn[i] - m);
    float inv_s = 1.0f / s;
    #pragma unroll
    for (int i = 0; i < S_; i++) {
        float sm  = expf(dn[i] - m) * inv_s;
        float sig = 1.0f / (1.0f + expf(-dn[i]));
        float a = sm * sig;
        attn_out[((size_t)b * S_ + i) * N_ + j] = a;
        __nv_bfloat16 h = __float2bfloat16(a);
        __nv_bfloat16 l = __float2bfloat16(a - __bfloat162float(h));
        g_ath[((size_t)b * 64 + i) * N_ + j] = h;
        g_atl[((size_t)b * 64 + i) * N_ + j] = l;
    }
}

// ---------------- updates via mma (single-sync pipeline) ------------------------
#define USTAGE 27648
#define USMEM  (2 * USTAGE)
__global__ __launch_bounds__(256, 2)
void sc_updates_mma(const float* __restrict__ inputs, float* __restrict__ out) {
    extern __shared__ char sm[];
    const int tid = threadIdx.x;
    const int wid = tid >> 5, lane = tid & 31;
    const int wm = wid & 1, wn = wid >> 1;
    const int b = blockIdx.y;
    const int dtile = blockIdx.x * 128;
    const uint32_t sb = smem_u32(sm);

    const __nv_bfloat16* Ah = g_ath + (size_t)b * 64 * N_;
    const __nv_bfloat16* Al = g_atl + (size_t)b * 64 * N_;
    const float* Bsrc = inputs + (size_t)b * N_ * D_ + dtile;

    const int arow = tid >> 2, ach = tid & 3;
    const int brow = tid >> 3, bdc = (tid & 7) * 16;

    float acc[2][4][4];
    #pragma unroll
    for (int a = 0; a < 2; a++)
        #pragma unroll
        for (int c = 0; c < 4; c++)
            #pragma unroll
            for (int e = 0; e < 4; e++) acc[a][c][e] = 0.0f;

    const uint32_t a_l = sb + (uint32_t)((wm * 32 + (lane & 15)) * 80 + (lane >> 4) * 16);
    const uint32_t b_l = sb + 10240u +
        (uint32_t)((((lane >> 3) & 1) * 8 + (lane & 7)) * 272 +
                   (wn * 32 + (lane >> 4) * 8) * 2);

    auto ISSUE_A = [&](int stage, int slab) {
        const uint32_t base = sb + (uint32_t)stage * USTAGE;
        uint32_t d0 = base + (uint32_t)arow * 80u + (uint32_t)ach * 16u;
        size_t s0 = (size_t)arow * N_ + slab * 32 + ach * 8;
        cp16(d0,         Ah + s0);
        cp16(d0 + 5120u, Al + s0);
        CP_COMMIT();
    };

    float4 breg[2][4];
    auto LDGB = [&](int slab, int buf) {
        const float* p = Bsrc + (size_t)(slab * 32 + brow) * D_ + bdc;
        #pragma unroll
        for (int q = 0; q < 4; q++) breg[buf][q] = *(const float4*)(p + q * 4);
    };
    auto STSB = [&](int stage, int buf) {
        const uint32_t off = (uint32_t)stage * USTAGE + 10240u +
                             (uint32_t)brow * 272u + (uint32_t)bdc * 2u;
        #pragma unroll
        for (int q = 0; q < 4; q++) {
            uint2 h, l;
            split4(breg[buf][q], h, l);
            *(uint2*)(sm + off + q * 8)         = h;
            *(uint2*)(sm + off + 8704u + q * 8) = l;
        }
    };

    auto COMP = [&](int stage) {
        uint32_t ab  = a_l + (uint32_t)stage * USTAGE;
        uint32_t bb_ = b_l + (uint32_t)stage * USTAGE;
        #pragma unroll
        for (int ks = 0; ks < 2; ks++) {
            uint32_t ak = ab + ks * 32;
            uint32_t bk = bb_ + ks * 16 * 272;
            uint32_t af[2][4], bh[2][4], bl[2][4];
            #pragma unroll
            for (int mf = 0; mf < 2; mf++) ldsm_x4(af[mf], ak + mf * 1280);
            #pragma unroll
            for (int p = 0; p < 2; p++) ldsm_x4_t(bh[p], bk + p * 32);
            #pragma unroll
            for (int mf = 0; mf < 2; mf++)
                #pragma unroll
                for (int nf = 0; nf < 4; nf++)
                    mma_bf16(acc[mf][nf], af[mf], &bh[nf >> 1][(nf & 1) * 2]);
            #pragma unroll
            for (int p = 0; p < 2; p++) ldsm_x4_t(bl[p], bk + 8704u + p * 32);
            #pragma unroll
            for (int mf = 0; mf < 2; mf++)
                #pragma unroll
                for (int nf = 0; nf < 4; nf++)
                    mma_bf16(acc[mf][nf], af[mf], &bl[nf >> 1][(nf & 1) * 2]);
            #pragma unroll
            for (int mf = 0; mf < 2; mf++) ldsm_x4(af[mf], ak + 5120u + mf * 1280);
            #pragma unroll
            for (int mf = 0; mf < 2; mf++)
                #pragma unroll
                for (int nf = 0; nf < 4; nf++)
                    mma_bf16(acc[mf][nf], af[mf], &bh[nf >> 1][(nf & 1) * 2]);
        }
    };

    LDGB(0, 0);
    LDGB(1, 1);
    ISSUE_A(0, 0);
    STSB(0, 0);

    for (int i = 0; i < 32; i++) {
        const int s = i & 1;
        CP_WAIT0();
        __syncthreads();
        if (i < 31) {
            ISSUE_A(s ^ 1, i + 1);
            STSB(s ^ 1, (i + 1) & 1);
        }
        if (i < 30) LDGB(i + 2, i & 1);
        COMP(s);
    }

    const float invd = 1.0f / (float)D_;
    #pragma unroll
    for (int mf = 0; mf < 2; mf++) {
        int i0 = wm * 32 + mf * 16 + (lane >> 2);
        #pragma unroll
        for (int nf = 0; nf < 4; nf++) {
            int col = dtile + wn * 32 + nf * 8 + (lane & 3) * 2;
            if (i0 < S_) {
                float2 v;
                v.x = acc[mf][nf][0] * invd;
                v.y = acc[mf][nf][1] * invd;
                *(float2*)&out[((size_t)b * S_ + i0) * D_ + col] = v;
            }
            if (i0 + 8 < S_) {
                float2 v;
                v.x = acc[mf][nf][2] * invd;
                v.y = acc[mf][nf][3] * invd;
                *(float2*)&out[((size_t)b * S_ + i0 + 8) * D_ + col] = v;
            }
        }
    }
}

// ---------------- launch ---------------------------------------------------------
extern "C" void kernel_launch(void* const* d_in, const int* in_sizes, int n_in,
                              void* d_out, int out_size) {
    const float* inputs_pe = (const float*)d_in[0];
    const float* inputs    = (const float*)d_in[1];
    const float* slots     = (const float*)d_in[2];
    const float* W1 = (const float*)d_in[3];
    const float* b1 = (const float*)d_in[4];
    const float* W2 = (const float*)d_in[5];
    const float* b2 = (const float*)d_in[6];
    const float* W3 = (const float*)d_in[7];
    const float* b3 = (const float*)d_in[8];
    float* out = (float*)d_out;

    __nv_bfloat16 *p0h, *p0l, *p1h, *p1l, *wh, *wl;
    float *attn_fb;
    cudaGetSymbolAddress((void**)&p0h, g_p0h);
    cudaGetSymbolAddress((void**)&p0l, g_p0l);
    cudaGetSymbolAddress((void**)&p1h, g_p1h);
    cudaGetSymbolAddress((void**)&p1l, g_p1l);
    cudaGetSymbolAddress((void**)&wh,  g_wh);
    cudaGetSymbolAddress((void**)&wl,  g_wl);
    cudaGetSymbolAddress((void**)&attn_fb, g_attn_fb);

    const size_t updates_elems = (size_t)B_ * S_ * D_;
    const size_t attn_elems    = (size_t)B_ * S_ * N_;
    float* attn_ptr = out + updates_elems;
    if ((size_t)out_size < updates_elems + attn_elems) attn_ptr = attn_fb;

    cudaFuncSetAttribute(sc_pipe_gemm<1>, cudaFuncAttributeMaxDynamicSharedMemorySize, GSMEM);
    cudaFuncSetAttribute(sc_dots_mma,     cudaFuncAttributeMaxDynamicSharedMemorySize, DSMEM);
    cudaFuncSetAttribute(sc_updates_mma,  cudaFuncAttributeMaxDynamicSharedMemorySize, USMEM);

    sc_zero_kernel<<<(B_ * 64 + 255) / 256, 256>>>();
    {
        int n4 = (M_ * D_) / 4;
        sc_split_kernel<<<(n4 + 255) / 256, 256>>>(inputs_pe, p0h, p0l, n4);
        int w4 = (D_ * D_) / 4;
        sc_split_kernel<<<(w4 + 255) / 256, 256>>>(W1, wh + 0 * D_ * D_, wl + 0 * D_ * D_, w4);
        sc_split_kernel<<<(w4 + 255) / 256, 256>>>(W2, wh + 1 * D_ * D_, wl + 1 * D_ * D_, w4);
    }
    {
        dim3 gv3(64, 8);
        sc_v3_kernel<<<gv3, 256>>>(slots, W3, b3);
    }

    dim3 gg(D_ / 128, M_ / 128);
    sc_pipe_gemm<1><<<gg, 256, GSMEM>>>(p0h, p0l, wh + 0 * D_ * D_, wl + 0 * D_ * D_, b1,
                                        p1h, p1l);
    sc_pipe_gemm<1><<<gg, 256, GSMEM>>>(p1h, p1l, wh + 1 * D_ * D_, wl + 1 * D_ * D_, b2,
                                        p0h, p0l);

    sc_dots_mma<<<M_ / 128, 256, DSMEM>>>(p0h, p0l);

    dim3 gsm(N_ / 128, B_);
    sc_softmax_kernel<<<gsm, 128>>>(attn_ptr);

    dim3 gup(D_ / 128, B_);
    sc_updates_mma<<<gup, 256, USMEM>>>(inputs, out);
}